// round 2
// baseline (speedup 1.0000x reference)
#include <cuda_runtime.h>
#include <cstdint>

// Problem constants (known shapes from the reference)
#define D        512        // feature dim (in == out)
#define MAXN     50000
#define MAXE     800000

// ---------------- device scratch (no allocations allowed) ----------------
__device__ float g_agg[(size_t)MAXN * D];   // aggregated messages  [N, 512]
__device__ float g_deg[MAXN];               // out-degree of each node (as source)
__device__ float g_norm[MAXE];              // per-edge norm coefficient
__device__ int   g_is64;                    // 1 if edge_index is int64, 0 if int32

// ---------------- dtype sniffer ----------------
// If edge_index is int64 (values < 2^31, nonneg), every odd 32-bit word of the
// buffer is 0. If int32, odd words are random node ids (P(all zero) ~ 0).
__global__ void detect_kernel(const int* __restrict__ ei32) {
    __shared__ int any_nonzero;
    if (threadIdx.x == 0) any_nonzero = 0;
    __syncthreads();
    int v = ei32[2 * threadIdx.x + 1];
    if (v != 0) atomicOr(&any_nonzero, 1);
    __syncthreads();
    if (threadIdx.x == 0) g_is64 = (any_nonzero == 0) ? 1 : 0;
}

__device__ __forceinline__ int load_idx(const void* ei, long long pos, int is64) {
    if (is64) return (int)((const long long*)ei)[pos];
    return ((const int*)ei)[pos];
}

// ---------------- zero scratch ----------------
__global__ void zero_kernel(int n_nodes) {
    size_t total = (size_t)n_nodes * D;
    size_t i = (size_t)blockIdx.x * blockDim.x + threadIdx.x;
    size_t stride = (size_t)gridDim.x * blockDim.x;
    float4 z = make_float4(0.f, 0.f, 0.f, 0.f);
    for (size_t k = i; k < total / 4; k += stride)
        ((float4*)g_agg)[k] = z;
    for (size_t k = i; k < (size_t)n_nodes; k += stride)
        g_deg[k] = 0.f;
}

// ---------------- degree ----------------
__global__ void deg_kernel(const void* __restrict__ ei, int E) {
    int e = blockIdx.x * blockDim.x + threadIdx.x;
    if (e >= E) return;
    int is64 = g_is64;
    int r = load_idx(ei, e, is64);
    atomicAdd(&g_deg[r], 1.0f);
}

// ---------------- per-edge norm = dis[row]*dis[col]*sigmoid(conf) ----------------
__global__ void norm_kernel(const void* __restrict__ ei,
                            const float* __restrict__ edge_attr,
                            const float* __restrict__ conf_w,
                            const float* __restrict__ conf_b,
                            int E) {
    int e = blockIdx.x * blockDim.x + threadIdx.x;
    if (e >= E) return;
    int is64 = g_is64;
    int r = load_idx(ei, e, is64);
    int c = load_idx(ei, (long long)E + e, is64);

    float z = edge_attr[3 * e + 0] * conf_w[0]
            + edge_attr[3 * e + 1] * conf_w[1]
            + edge_attr[3 * e + 2] * conf_w[2]
            + conf_b[0];
    float ew = 1.0f / (1.0f + expf(-z));

    float dr = g_deg[r];
    float dc = g_deg[c];
    float ir = (dr > 0.f) ? rsqrtf(dr) : 0.f;
    float ic = (dc > 0.f) ? rsqrtf(dc) : 0.f;
    float nrm = ir * ic * ew;
    if (isnan(nrm)) nrm = 0.f;
    g_norm[e] = nrm;
}

// ---------------- scatter: agg[col] += x[row] * norm  (one warp per edge) ----------------
__global__ void scatter_kernel(const float* __restrict__ x,
                               const void* __restrict__ ei,
                               int E) {
    int warp = (blockIdx.x * blockDim.x + threadIdx.x) >> 5;
    int lane = threadIdx.x & 31;
    if (warp >= E) return;
    float nrm = g_norm[warp];
    if (nrm == 0.f) return;
    int is64 = g_is64;
    int r = load_idx(ei, warp, is64);
    int c = load_idx(ei, (long long)E + warp, is64);

    const float4* __restrict__ xr = (const float4*)(x + (size_t)r * D);
    float* dst = g_agg + (size_t)c * D;
#pragma unroll
    for (int i = 0; i < 4; i++) {
        int off = lane + i * 32;         // float4 index within row (0..127)
        float4 v = xr[off];
        float* p = dst + off * 4;
        asm volatile("red.global.add.v4.f32 [%0], {%1, %2, %3, %4};"
                     :: "l"(p), "f"(v.x * nrm), "f"(v.y * nrm),
                        "f"(v.z * nrm), "f"(v.w * nrm)
                     : "memory");
    }
}

// ---------------- GEMM: out[n, j] = sum_k agg[n,k] * W[j,k] + b[j] ----------------
// Classic 128x128x8 SIMT SGEMM, 256 threads, 8x8 per thread.
// NOTE: reads g_agg as a device symbol directly (passing it from host is UB).
__global__ void __launch_bounds__(256)
gemm_kernel(const float* __restrict__ W,     // [512, 512] row-major, W[j,k]
            const float* __restrict__ bias,  // [512]
            float* __restrict__ out,         // [N, 512]
            int Nrows) {
    const float* __restrict__ A = g_agg;     // [N, 512]

    __shared__ float As[8][128];
    __shared__ float Bs[8][128];

    const int tid = threadIdx.x;
    const int n0 = blockIdx.x * 128;
    const int j0 = blockIdx.y * 128;

    const int ldRow = tid >> 1;          // 0..127
    const int ldCol = (tid & 1) * 4;     // 0 or 4

    const int tx = tid & 15;             // col group (x8)
    const int ty = tid >> 4;             // row group (x8)

    float acc[8][8];
#pragma unroll
    for (int i = 0; i < 8; i++)
#pragma unroll
        for (int j = 0; j < 8; j++) acc[i][j] = 0.f;

    for (int k0 = 0; k0 < 512; k0 += 8) {
        // Load A tile (transposed into smem), guard rows
        float4 av = make_float4(0.f, 0.f, 0.f, 0.f);
        int grow = n0 + ldRow;
        if (grow < Nrows)
            av = *(const float4*)(A + (size_t)grow * D + k0 + ldCol);
        As[ldCol + 0][ldRow] = av.x;
        As[ldCol + 1][ldRow] = av.y;
        As[ldCol + 2][ldRow] = av.z;
        As[ldCol + 3][ldRow] = av.w;

        // Load B tile: Bs[k][j] = W[j0+j, k0+k]
        float4 bv = *(const float4*)(W + (size_t)(j0 + ldRow) * D + k0 + ldCol);
        Bs[ldCol + 0][ldRow] = bv.x;
        Bs[ldCol + 1][ldRow] = bv.y;
        Bs[ldCol + 2][ldRow] = bv.z;
        Bs[ldCol + 3][ldRow] = bv.w;

        __syncthreads();

#pragma unroll
        for (int k = 0; k < 8; k++) {
            float ra[8], rb[8];
#pragma unroll
            for (int i = 0; i < 8; i++) ra[i] = As[k][ty * 8 + i];
#pragma unroll
            for (int j = 0; j < 8; j++) rb[j] = Bs[k][tx * 8 + j];
#pragma unroll
            for (int i = 0; i < 8; i++)
#pragma unroll
                for (int j = 0; j < 8; j++)
                    acc[i][j] = fmaf(ra[i], rb[j], acc[i][j]);
        }
        __syncthreads();
    }

    // Epilogue: add bias, vectorized stores
#pragma unroll
    for (int i = 0; i < 8; i++) {
        int row = n0 + ty * 8 + i;
        if (row >= Nrows) continue;
        float* orow = out + (size_t)row * D + j0 + tx * 8;
        float4 v0, v1;
        v0.x = acc[i][0] + bias[j0 + tx * 8 + 0];
        v0.y = acc[i][1] + bias[j0 + tx * 8 + 1];
        v0.z = acc[i][2] + bias[j0 + tx * 8 + 2];
        v0.w = acc[i][3] + bias[j0 + tx * 8 + 3];
        v1.x = acc[i][4] + bias[j0 + tx * 8 + 4];
        v1.y = acc[i][5] + bias[j0 + tx * 8 + 5];
        v1.z = acc[i][6] + bias[j0 + tx * 8 + 6];
        v1.w = acc[i][7] + bias[j0 + tx * 8 + 7];
        ((float4*)orow)[0] = v0;
        ((float4*)orow)[1] = v1;
    }
}

// ---------------- launch ----------------
extern "C" void kernel_launch(void* const* d_in, const int* in_sizes, int n_in,
                              void* d_out, int out_size) {
    const float* x         = (const float*)d_in[0];
    const void*  ei        = d_in[1];                 // int32 or int64, sniffed on device
    const float* edge_attr = (const float*)d_in[2];
    const float* lin_w     = (const float*)d_in[3];
    const float* lin_b     = (const float*)d_in[4];
    const float* conf_w    = (const float*)d_in[5];
    const float* conf_b    = (const float*)d_in[6];
    float* out             = (float*)d_out;

    const int n_nodes = in_sizes[0] / D;
    const int E       = in_sizes[2] / 3;

    detect_kernel<<<1, 256>>>((const int*)ei);

    {
        int blocks = 1024;
        zero_kernel<<<blocks, 256>>>(n_nodes);
    }

    {
        int blocks = (E + 255) / 256;
        deg_kernel<<<blocks, 256>>>(ei, E);
        norm_kernel<<<blocks, 256>>>(ei, edge_attr, conf_w, conf_b, E);
    }

    {
        // one warp per edge
        int warps_per_block = 256 / 32;
        int blocks = (E + warps_per_block - 1) / warps_per_block;
        scatter_kernel<<<blocks, 256>>>(x, ei, E);
    }

    {
        dim3 grid((n_nodes + 127) / 128, D / 128);
        gemm_kernel<<<grid, 256>>>(lin_w, lin_b, out, n_nodes);
    }
}

// round 3
// speedup vs baseline: 1.7896x; 1.7896x over previous
#include <cuda_runtime.h>
#include <cstdint>

// Problem constants (known shapes from the reference)
#define D        512        // feature dim (in == out)
#define MAXN     50000
#define MAXE     800000

// ---------------- device scratch (no allocations allowed) ----------------
__device__ float g_agg[(size_t)MAXN * D];   // aggregated messages  [N, 512]
__device__ float g_deg[MAXN];               // out-degree of each node (as source)
__device__ float g_norm[MAXE];              // per-edge norm coefficient
__device__ int   g_is64;                    // 1 if edge_index is int64, 0 if int32

// ---------------- dtype sniffer ----------------
__global__ void detect_kernel(const int* __restrict__ ei32) {
    __shared__ int any_nonzero;
    if (threadIdx.x == 0) any_nonzero = 0;
    __syncthreads();
    int v = ei32[2 * threadIdx.x + 1];
    if (v != 0) atomicOr(&any_nonzero, 1);
    __syncthreads();
    if (threadIdx.x == 0) g_is64 = (any_nonzero == 0) ? 1 : 0;
}

__device__ __forceinline__ int load_idx(const void* ei, long long pos, int is64) {
    if (is64) return (int)((const long long*)ei)[pos];
    return ((const int*)ei)[pos];
}

// ---------------- zero scratch ----------------
__global__ void zero_kernel(int n_nodes) {
    size_t total = (size_t)n_nodes * D;
    size_t i = (size_t)blockIdx.x * blockDim.x + threadIdx.x;
    size_t stride = (size_t)gridDim.x * blockDim.x;
    float4 z = make_float4(0.f, 0.f, 0.f, 0.f);
    for (size_t k = i; k < total / 4; k += stride)
        ((float4*)g_agg)[k] = z;
    for (size_t k = i; k < (size_t)n_nodes; k += stride)
        g_deg[k] = 0.f;
}

// ---------------- degree ----------------
__global__ void deg_kernel(const void* __restrict__ ei, int E) {
    int e = blockIdx.x * blockDim.x + threadIdx.x;
    if (e >= E) return;
    int is64 = g_is64;
    int r = load_idx(ei, e, is64);
    atomicAdd(&g_deg[r], 1.0f);
}

// ---------------- per-edge norm ----------------
__global__ void norm_kernel(const void* __restrict__ ei,
                            const float* __restrict__ edge_attr,
                            const float* __restrict__ conf_w,
                            const float* __restrict__ conf_b,
                            int E) {
    int e = blockIdx.x * blockDim.x + threadIdx.x;
    if (e >= E) return;
    int is64 = g_is64;
    int r = load_idx(ei, e, is64);
    int c = load_idx(ei, (long long)E + e, is64);

    float z = edge_attr[3 * e + 0] * conf_w[0]
            + edge_attr[3 * e + 1] * conf_w[1]
            + edge_attr[3 * e + 2] * conf_w[2]
            + conf_b[0];
    float ew = 1.0f / (1.0f + expf(-z));

    float dr = g_deg[r];
    float dc = g_deg[c];
    float ir = (dr > 0.f) ? rsqrtf(dr) : 0.f;
    float ic = (dc > 0.f) ? rsqrtf(dc) : 0.f;
    float nrm = ir * ic * ew;
    if (isnan(nrm)) nrm = 0.f;
    g_norm[e] = nrm;
}

// ---------------- scatter: agg[col] += x[row] * norm (one warp per edge) ----------------
__global__ void scatter_kernel(const float* __restrict__ x,
                               const void* __restrict__ ei,
                               int E) {
    int warp = (blockIdx.x * blockDim.x + threadIdx.x) >> 5;
    int lane = threadIdx.x & 31;
    if (warp >= E) return;
    float nrm = g_norm[warp];
    if (nrm == 0.f) return;
    int is64 = g_is64;
    int r = load_idx(ei, warp, is64);
    int c = load_idx(ei, (long long)E + warp, is64);

    const float4* __restrict__ xr = (const float4*)(x + (size_t)r * D);
    float* dst = g_agg + (size_t)c * D;
#pragma unroll
    for (int i = 0; i < 4; i++) {
        int off = lane + i * 32;
        float4 v = xr[off];
        float* p = dst + off * 4;
        asm volatile("red.global.add.v4.f32 [%0], {%1, %2, %3, %4};"
                     :: "l"(p), "f"(v.x * nrm), "f"(v.y * nrm),
                        "f"(v.z * nrm), "f"(v.w * nrm)
                     : "memory");
    }
}

// ---------------- TF32 tensor-core GEMM: out = agg @ W^T + b ----------------
// Block tile 128(m) x 64(n), 4 warps (2x2), warp tile 64x32.
// K-chunk 16, double-buffered cp.async. mma.sync m16n8k8 tf32 (truncated f32).
#define KC       16            // k per chunk
#define ROWPITCH 20            // floats per smem row (16 data + 4 pad; (4r+c)%32 distinct)

__device__ __forceinline__ void cp_async16(uint32_t smem, const void* gptr, int valid) {
    asm volatile("cp.async.cg.shared.global [%0], [%1], 16, %2;\n"
                 :: "r"(smem), "l"(gptr), "r"(valid ? 16 : 0));
}
__device__ __forceinline__ void cp_commit() {
    asm volatile("cp.async.commit_group;\n" ::: "memory");
}
__device__ __forceinline__ void cp_wait1() {
    asm volatile("cp.async.wait_group 1;\n" ::: "memory");
}

__global__ void __launch_bounds__(128)
gemm_tf32_kernel(const float* __restrict__ W,     // [512, 512] row-major W[j,k]
                 const float* __restrict__ bias,  // [512]
                 float* __restrict__ out,         // [N, 512]
                 int Nrows) {
    const float* __restrict__ A = g_agg;

    __shared__ float As[2][128 * ROWPITCH];
    __shared__ float Bs[2][64 * ROWPITCH];

    const int tid  = threadIdx.x;
    const int warp = tid >> 5;
    const int lane = tid & 31;
    const int g    = lane >> 2;   // 0..7
    const int tg   = lane & 3;    // 0..3
    const int wm   = warp >> 1;   // 0..1
    const int wn   = warp & 1;    // 0..1
    const int m0   = blockIdx.x * 128;
    const int n0   = blockIdx.y * 64;

    float acc[4][4][4];
#pragma unroll
    for (int i = 0; i < 4; i++)
#pragma unroll
        for (int j = 0; j < 4; j++)
#pragma unroll
            for (int r = 0; r < 4; r++) acc[i][j][r] = 0.f;

    // --- tile loader: A 128x16 (4 float4/thread), B 64x16 (2 float4/thread) ---
    uint32_t sA0 = (uint32_t)__cvta_generic_to_shared(&As[0][0]);
    uint32_t sA1 = (uint32_t)__cvta_generic_to_shared(&As[1][0]);
    uint32_t sB0 = (uint32_t)__cvta_generic_to_shared(&Bs[0][0]);
    uint32_t sB1 = (uint32_t)__cvta_generic_to_shared(&Bs[1][0]);

#define ISSUE_TILE(buf, k0)                                                        \
    do {                                                                           \
        uint32_t sa = (buf) ? sA1 : sA0;                                           \
        uint32_t sb = (buf) ? sB1 : sB0;                                           \
        _Pragma("unroll")                                                          \
        for (int i = 0; i < 4; i++) {                                              \
            int idx = i * 128 + tid;                                               \
            int row = idx >> 2, c4 = idx & 3;                                      \
            int grow = m0 + row;                                                   \
            const float* gp = A + (size_t)grow * D + (k0) + c4 * 4;                \
            cp_async16(sa + (row * ROWPITCH + c4 * 4) * 4, gp, grow < Nrows);      \
        }                                                                          \
        _Pragma("unroll")                                                          \
        for (int i = 0; i < 2; i++) {                                              \
            int idx = i * 128 + tid;                                               \
            int row = idx >> 2, c4 = idx & 3;                                      \
            const float* gp = W + (size_t)(n0 + row) * D + (k0) + c4 * 4;          \
            cp_async16(sb + (row * ROWPITCH + c4 * 4) * 4, gp, 1);                 \
        }                                                                          \
    } while (0)

    ISSUE_TILE(0, 0);
    cp_commit();

    const int NCHUNK = D / KC;  // 32
    for (int kc = 0; kc < NCHUNK; kc++) {
        int buf = kc & 1;
        if (kc + 1 < NCHUNK) ISSUE_TILE((kc + 1) & 1, (kc + 1) * KC);
        cp_commit();
        cp_wait1();
        __syncthreads();

        const float* as = As[buf];
        const float* bs = Bs[buf];

#pragma unroll
        for (int ks = 0; ks < 2; ks++) {
            int k = ks * 8;
            uint32_t af[4][4], bf[4][2];
#pragma unroll
            for (int mi = 0; mi < 4; mi++) {
                int rb = wm * 64 + mi * 16;
                af[mi][0] = __float_as_uint(as[(rb + g) * ROWPITCH + k + tg]);
                af[mi][1] = __float_as_uint(as[(rb + g + 8) * ROWPITCH + k + tg]);
                af[mi][2] = __float_as_uint(as[(rb + g) * ROWPITCH + k + tg + 4]);
                af[mi][3] = __float_as_uint(as[(rb + g + 8) * ROWPITCH + k + tg + 4]);
            }
#pragma unroll
            for (int nj = 0; nj < 4; nj++) {
                int nb = wn * 32 + nj * 8;
                bf[nj][0] = __float_as_uint(bs[(nb + g) * ROWPITCH + k + tg]);
                bf[nj][1] = __float_as_uint(bs[(nb + g) * ROWPITCH + k + tg + 4]);
            }
#pragma unroll
            for (int mi = 0; mi < 4; mi++)
#pragma unroll
                for (int nj = 0; nj < 4; nj++) {
                    asm volatile(
                        "mma.sync.aligned.m16n8k8.row.col.f32.tf32.tf32.f32 "
                        "{%0,%1,%2,%3}, {%4,%5,%6,%7}, {%8,%9}, {%0,%1,%2,%3};"
                        : "+f"(acc[mi][nj][0]), "+f"(acc[mi][nj][1]),
                          "+f"(acc[mi][nj][2]), "+f"(acc[mi][nj][3])
                        : "r"(af[mi][0]), "r"(af[mi][1]), "r"(af[mi][2]), "r"(af[mi][3]),
                          "r"(bf[nj][0]), "r"(bf[nj][1]));
                }
        }
        __syncthreads();
    }

    // Epilogue: bias + store (float2 per fragment half)
#pragma unroll
    for (int mi = 0; mi < 4; mi++) {
        int r0 = m0 + wm * 64 + mi * 16 + g;
        int r1 = r0 + 8;
#pragma unroll
        for (int nj = 0; nj < 4; nj++) {
            int cn = n0 + wn * 32 + nj * 8 + 2 * tg;
            float2 bb = *(const float2*)(bias + cn);
            if (r0 < Nrows) {
                float2 v = make_float2(acc[mi][nj][0] + bb.x, acc[mi][nj][1] + bb.y);
                *(float2*)(out + (size_t)r0 * D + cn) = v;
            }
            if (r1 < Nrows) {
                float2 v = make_float2(acc[mi][nj][2] + bb.x, acc[mi][nj][3] + bb.y);
                *(float2*)(out + (size_t)r1 * D + cn) = v;
            }
        }
    }
#undef ISSUE_TILE
}

// ---------------- launch ----------------
extern "C" void kernel_launch(void* const* d_in, const int* in_sizes, int n_in,
                              void* d_out, int out_size) {
    const float* x         = (const float*)d_in[0];
    const void*  ei        = d_in[1];
    const float* edge_attr = (const float*)d_in[2];
    const float* lin_w     = (const float*)d_in[3];
    const float* lin_b     = (const float*)d_in[4];
    const float* conf_w    = (const float*)d_in[5];
    const float* conf_b    = (const float*)d_in[6];
    float* out             = (float*)d_out;

    const int n_nodes = in_sizes[0] / D;
    const int E       = in_sizes[2] / 3;

    detect_kernel<<<1, 256>>>((const int*)ei);
    zero_kernel<<<1024, 256>>>(n_nodes);

    {
        int blocks = (E + 255) / 256;
        deg_kernel<<<blocks, 256>>>(ei, E);
        norm_kernel<<<blocks, 256>>>(ei, edge_attr, conf_w, conf_b, E);
    }

    {
        int warps_per_block = 256 / 32;
        int blocks = (E + warps_per_block - 1) / warps_per_block;
        scatter_kernel<<<blocks, 256>>>(x, ei, E);
    }

    {
        dim3 grid((n_nodes + 127) / 128, D / 64);
        gemm_tf32_kernel<<<grid, 128>>>(lin_w, lin_b, out, n_nodes);
    }
}

// round 4
// speedup vs baseline: 2.8711x; 1.6043x over previous
#include <cuda_runtime.h>
#include <cstdint>

#define D        512
#define MAXN     50000
#define MAXE     800000

// ---------------- device scratch ----------------
__device__ float g_agg[(size_t)MAXN * D];   // aggregated messages [N, 512]
__device__ float g_deg[MAXN];               // source-degree (row histogram, as float)
__device__ float g_norm[MAXE];              // per-edge norm
__device__ int   g_cnt[MAXN];               // col histogram
__device__ int   g_off[MAXN + 1];           // CSC offsets
__device__ int   g_cur[MAXN];               // fill cursors
__device__ int   g_srow[MAXE];              // source row, sorted by destination
__device__ float g_snorm[MAXE];             // norm, sorted by destination
__device__ int   g_is64;

// ---------------- dtype sniffer ----------------
__global__ void detect_kernel(const int* __restrict__ ei32) {
    __shared__ int any_nonzero;
    if (threadIdx.x == 0) any_nonzero = 0;
    __syncthreads();
    int v = ei32[2 * threadIdx.x + 1];
    if (v != 0) atomicOr(&any_nonzero, 1);
    __syncthreads();
    if (threadIdx.x == 0) g_is64 = (any_nonzero == 0) ? 1 : 0;
}

__device__ __forceinline__ int load_idx(const void* ei, long long pos, int is64) {
    if (is64) return (int)((const long long*)ei)[pos];
    return ((const int*)ei)[pos];
}

// ---------------- zero the small arrays (not g_agg!) ----------------
__global__ void zero_small_kernel(int n_nodes) {
    int i = blockIdx.x * blockDim.x + threadIdx.x;
    if (i < n_nodes) {
        g_deg[i] = 0.f;
        g_cnt[i] = 0;
        g_cur[i] = 0;
    }
}

// ---------------- histograms: deg[row] (float), cnt[col] (int) ----------------
__global__ void hist_kernel(const void* __restrict__ ei, int E) {
    int e = blockIdx.x * blockDim.x + threadIdx.x;
    if (e >= E) return;
    int is64 = g_is64;
    int r = load_idx(ei, e, is64);
    int c = load_idx(ei, (long long)E + e, is64);
    atomicAdd(&g_deg[r], 1.0f);
    atomicAdd(&g_cnt[c], 1);
}

// ---------------- per-edge norm ----------------
__global__ void norm_kernel(const void* __restrict__ ei,
                            const float* __restrict__ edge_attr,
                            const float* __restrict__ conf_w,
                            const float* __restrict__ conf_b,
                            int E) {
    int e = blockIdx.x * blockDim.x + threadIdx.x;
    if (e >= E) return;
    int is64 = g_is64;
    int r = load_idx(ei, e, is64);
    int c = load_idx(ei, (long long)E + e, is64);

    float z = edge_attr[3 * e + 0] * conf_w[0]
            + edge_attr[3 * e + 1] * conf_w[1]
            + edge_attr[3 * e + 2] * conf_w[2]
            + conf_b[0];
    float ew = 1.0f / (1.0f + expf(-z));

    float dr = g_deg[r];
    float dc = g_deg[c];
    float ir = (dr > 0.f) ? rsqrtf(dr) : 0.f;
    float ic = (dc > 0.f) ? rsqrtf(dc) : 0.f;
    float nrm = ir * ic * ew;
    if (isnan(nrm)) nrm = 0.f;
    g_norm[e] = nrm;
}

// ---------------- exclusive scan of g_cnt into g_off (single block, shfl) ----------------
__global__ void __launch_bounds__(1024)
scan_kernel(int n) {
    __shared__ int warpsum[32];
    __shared__ int s_carry;
    const int tid  = threadIdx.x;
    const int lane = tid & 31;
    const int wid  = tid >> 5;
    if (tid == 0) { s_carry = 0; g_off[0] = 0; }
    __syncthreads();

    for (int base = 0; base < n; base += 1024) {
        int i = base + tid;
        int v = (i < n) ? g_cnt[i] : 0;
        // warp inclusive scan
#pragma unroll
        for (int d = 1; d < 32; d <<= 1) {
            int t = __shfl_up_sync(0xffffffffu, v, d);
            if (lane >= d) v += t;
        }
        if (lane == 31) warpsum[wid] = v;
        __syncthreads();
        if (wid == 0) {
            int s = warpsum[lane];
#pragma unroll
            for (int d = 1; d < 32; d <<= 1) {
                int t = __shfl_up_sync(0xffffffffu, s, d);
                if (lane >= d) s += t;
            }
            warpsum[lane] = s;
        }
        __syncthreads();
        int add = (wid > 0) ? warpsum[wid - 1] : 0;
        int incl = s_carry + add + v;
        if (i < n) g_off[i + 1] = incl;
        __syncthreads();
        if (tid == 1023) s_carry = incl;
        __syncthreads();
    }
}

// ---------------- fill CSC buckets ----------------
__global__ void fill_kernel(const void* __restrict__ ei, int E) {
    int e = blockIdx.x * blockDim.x + threadIdx.x;
    if (e >= E) return;
    int is64 = g_is64;
    int r = load_idx(ei, e, is64);
    int c = load_idx(ei, (long long)E + e, is64);
    int pos = g_off[c] + atomicAdd(&g_cur[c], 1);
    g_srow[pos]  = r;
    g_snorm[pos] = g_norm[e];
}

// ---------------- aggregate: one warp per destination node, write once ----------------
__global__ void __launch_bounds__(256)
aggregate_kernel(const float* __restrict__ x, int n_nodes) {
    int node = (blockIdx.x * blockDim.x + threadIdx.x) >> 5;
    int lane = threadIdx.x & 31;
    if (node >= n_nodes) return;

    int beg = g_off[node];
    int end = g_off[node + 1];

    float4 a0 = make_float4(0.f, 0.f, 0.f, 0.f);
    float4 a1 = a0, a2 = a0, a3 = a0;

    for (int i = beg; i < end; i++) {
        int   r  = g_srow[i];
        float nm = g_snorm[i];
        const float4* xr = (const float4*)(x + (size_t)r * D);
        float4 v0 = xr[lane];
        float4 v1 = xr[lane + 32];
        float4 v2 = xr[lane + 64];
        float4 v3 = xr[lane + 96];
        a0.x = fmaf(v0.x, nm, a0.x); a0.y = fmaf(v0.y, nm, a0.y);
        a0.z = fmaf(v0.z, nm, a0.z); a0.w = fmaf(v0.w, nm, a0.w);
        a1.x = fmaf(v1.x, nm, a1.x); a1.y = fmaf(v1.y, nm, a1.y);
        a1.z = fmaf(v1.z, nm, a1.z); a1.w = fmaf(v1.w, nm, a1.w);
        a2.x = fmaf(v2.x, nm, a2.x); a2.y = fmaf(v2.y, nm, a2.y);
        a2.z = fmaf(v2.z, nm, a2.z); a2.w = fmaf(v2.w, nm, a2.w);
        a3.x = fmaf(v3.x, nm, a3.x); a3.y = fmaf(v3.y, nm, a3.y);
        a3.z = fmaf(v3.z, nm, a3.z); a3.w = fmaf(v3.w, nm, a3.w);
    }

    float4* dst = (float4*)(g_agg + (size_t)node * D);
    dst[lane]      = a0;
    dst[lane + 32] = a1;
    dst[lane + 64] = a2;
    dst[lane + 96] = a3;
}

// ---------------- TF32 tensor-core GEMM: out = agg @ W^T + b ----------------
#define KC       16
#define ROWPITCH 20

__device__ __forceinline__ void cp_async16(uint32_t smem, const void* gptr, int valid) {
    asm volatile("cp.async.cg.shared.global [%0], [%1], 16, %2;\n"
                 :: "r"(smem), "l"(gptr), "r"(valid ? 16 : 0));
}
__device__ __forceinline__ void cp_commit() {
    asm volatile("cp.async.commit_group;\n" ::: "memory");
}
__device__ __forceinline__ void cp_wait1() {
    asm volatile("cp.async.wait_group 1;\n" ::: "memory");
}
__device__ __forceinline__ uint32_t f2tf32(float f) {
    uint32_t u;
    asm("cvt.rna.tf32.f32 %0, %1;" : "=r"(u) : "f"(f));
    return u;
}

__global__ void __launch_bounds__(128)
gemm_tf32_kernel(const float* __restrict__ W,
                 const float* __restrict__ bias,
                 float* __restrict__ out,
                 int Nrows) {
    const float* __restrict__ A = g_agg;

    __shared__ float As[2][128 * ROWPITCH];
    __shared__ float Bs[2][64 * ROWPITCH];

    const int tid  = threadIdx.x;
    const int warp = tid >> 5;
    const int lane = tid & 31;
    const int g    = lane >> 2;
    const int tg   = lane & 3;
    const int wm   = warp >> 1;
    const int wn   = warp & 1;
    const int m0   = blockIdx.x * 128;
    const int n0   = blockIdx.y * 64;

    float acc[4][4][4];
#pragma unroll
    for (int i = 0; i < 4; i++)
#pragma unroll
        for (int j = 0; j < 4; j++)
#pragma unroll
            for (int r = 0; r < 4; r++) acc[i][j][r] = 0.f;

    uint32_t sA0 = (uint32_t)__cvta_generic_to_shared(&As[0][0]);
    uint32_t sA1 = (uint32_t)__cvta_generic_to_shared(&As[1][0]);
    uint32_t sB0 = (uint32_t)__cvta_generic_to_shared(&Bs[0][0]);
    uint32_t sB1 = (uint32_t)__cvta_generic_to_shared(&Bs[1][0]);

#define ISSUE_TILE(buf, k0)                                                        \
    do {                                                                           \
        uint32_t sa = (buf) ? sA1 : sA0;                                           \
        uint32_t sb = (buf) ? sB1 : sB0;                                           \
        _Pragma("unroll")                                                          \
        for (int i = 0; i < 4; i++) {                                              \
            int idx = i * 128 + tid;                                               \
            int row = idx >> 2, c4 = idx & 3;                                      \
            int grow = m0 + row;                                                   \
            const float* gp = A + (size_t)grow * D + (k0) + c4 * 4;                \
            cp_async16(sa + (row * ROWPITCH + c4 * 4) * 4, gp, grow < Nrows);      \
        }                                                                          \
        _Pragma("unroll")                                                          \
        for (int i = 0; i < 2; i++) {                                              \
            int idx = i * 128 + tid;                                               \
            int row = idx >> 2, c4 = idx & 3;                                      \
            const float* gp = W + (size_t)(n0 + row) * D + (k0) + c4 * 4;          \
            cp_async16(sb + (row * ROWPITCH + c4 * 4) * 4, gp, 1);                 \
        }                                                                          \
    } while (0)

    ISSUE_TILE(0, 0);
    cp_commit();

    const int NCHUNK = D / KC;
    for (int kc = 0; kc < NCHUNK; kc++) {
        int buf = kc & 1;
        if (kc + 1 < NCHUNK) ISSUE_TILE((kc + 1) & 1, (kc + 1) * KC);
        cp_commit();
        cp_wait1();
        __syncthreads();

        const float* as = As[buf];
        const float* bs = Bs[buf];

#pragma unroll
        for (int ks = 0; ks < 2; ks++) {
            int k = ks * 8;
            uint32_t af[4][4], bf[4][2];
#pragma unroll
            for (int mi = 0; mi < 4; mi++) {
                int rb = wm * 64 + mi * 16;
                af[mi][0] = f2tf32(as[(rb + g) * ROWPITCH + k + tg]);
                af[mi][1] = f2tf32(as[(rb + g + 8) * ROWPITCH + k + tg]);
                af[mi][2] = f2tf32(as[(rb + g) * ROWPITCH + k + tg + 4]);
                af[mi][3] = f2tf32(as[(rb + g + 8) * ROWPITCH + k + tg + 4]);
            }
#pragma unroll
            for (int nj = 0; nj < 4; nj++) {
                int nb = wn * 32 + nj * 8;
                bf[nj][0] = f2tf32(bs[(nb + g) * ROWPITCH + k + tg]);
                bf[nj][1] = f2tf32(bs[(nb + g) * ROWPITCH + k + tg + 4]);
            }
#pragma unroll
            for (int mi = 0; mi < 4; mi++)
#pragma unroll
                for (int nj = 0; nj < 4; nj++) {
                    asm volatile(
                        "mma.sync.aligned.m16n8k8.row.col.f32.tf32.tf32.f32 "
                        "{%0,%1,%2,%3}, {%4,%5,%6,%7}, {%8,%9}, {%0,%1,%2,%3};"
                        : "+f"(acc[mi][nj][0]), "+f"(acc[mi][nj][1]),
                          "+f"(acc[mi][nj][2]), "+f"(acc[mi][nj][3])
                        : "r"(af[mi][0]), "r"(af[mi][1]), "r"(af[mi][2]), "r"(af[mi][3]),
                          "r"(bf[nj][0]), "r"(bf[nj][1]));
                }
        }
        __syncthreads();
    }

#pragma unroll
    for (int mi = 0; mi < 4; mi++) {
        int r0 = m0 + wm * 64 + mi * 16 + g;
        int r1 = r0 + 8;
#pragma unroll
        for (int nj = 0; nj < 4; nj++) {
            int cn = n0 + wn * 32 + nj * 8 + 2 * tg;
            float2 bb = *(const float2*)(bias + cn);
            if (r0 < Nrows) {
                float2 v = make_float2(acc[mi][nj][0] + bb.x, acc[mi][nj][1] + bb.y);
                *(float2*)(out + (size_t)r0 * D + cn) = v;
            }
            if (r1 < Nrows) {
                float2 v = make_float2(acc[mi][nj][2] + bb.x, acc[mi][nj][3] + bb.y);
                *(float2*)(out + (size_t)r1 * D + cn) = v;
            }
        }
    }
#undef ISSUE_TILE
}

// ---------------- launch ----------------
extern "C" void kernel_launch(void* const* d_in, const int* in_sizes, int n_in,
                              void* d_out, int out_size) {
    const float* x         = (const float*)d_in[0];
    const void*  ei        = d_in[1];
    const float* edge_attr = (const float*)d_in[2];
    const float* lin_w     = (const float*)d_in[3];
    const float* lin_b     = (const float*)d_in[4];
    const float* conf_w    = (const float*)d_in[5];
    const float* conf_b    = (const float*)d_in[6];
    float* out             = (float*)d_out;

    const int n_nodes = in_sizes[0] / D;
    const int E       = in_sizes[2] / 3;

    detect_kernel<<<1, 256>>>((const int*)ei);
    zero_small_kernel<<<(n_nodes + 255) / 256, 256>>>(n_nodes);

    int eblocks = (E + 255) / 256;
    hist_kernel<<<eblocks, 256>>>(ei, E);
    norm_kernel<<<eblocks, 256>>>(ei, edge_attr, conf_w, conf_b, E);
    scan_kernel<<<1, 1024>>>(n_nodes);
    fill_kernel<<<eblocks, 256>>>(ei, E);

    {
        int warps_per_block = 256 / 32;
        int blocks = (n_nodes + warps_per_block - 1) / warps_per_block;
        aggregate_kernel<<<blocks, 256>>>(x, n_nodes);
    }

    {
        dim3 grid((n_nodes + 127) / 128, D / 64);
        gemm_tf32_kernel<<<grid, 128>>>(lin_w, lin_b, out, n_nodes);
    }
}

// round 5
// speedup vs baseline: 2.8857x; 1.0051x over previous
#include <cuda_runtime.h>
#include <cstdint>

#define D        512
#define MAXN     50000
#define MAXE     800000

// ---------------- device scratch ----------------
__device__ float g_agg[(size_t)MAXN * D];   // aggregated messages [N, 512]
__device__ float g_deg[MAXN];               // source-degree (row histogram, as float)
__device__ int   g_cnt[MAXN];               // col histogram
__device__ int   g_off[MAXN + 1];           // CSC offsets
__device__ int   g_cur[MAXN];               // fill cursors
__device__ int   g_srow[MAXE];              // source row, sorted by destination
__device__ float g_snorm[MAXE];             // norm, sorted by destination
__device__ int   g_is64;

// ---------------- dtype sniffer ----------------
__global__ void detect_kernel(const int* __restrict__ ei32) {
    __shared__ int any_nonzero;
    if (threadIdx.x == 0) any_nonzero = 0;
    __syncthreads();
    int v = ei32[2 * threadIdx.x + 1];
    if (v != 0) atomicOr(&any_nonzero, 1);
    __syncthreads();
    if (threadIdx.x == 0) g_is64 = (any_nonzero == 0) ? 1 : 0;
}

__device__ __forceinline__ int load_idx(const void* ei, long long pos, int is64) {
    if (is64) return (int)((const long long*)ei)[pos];
    return ((const int*)ei)[pos];
}

// ---------------- zero the small arrays ----------------
__global__ void zero_small_kernel(int n_nodes) {
    int i = blockIdx.x * blockDim.x + threadIdx.x;
    if (i < n_nodes) {
        g_deg[i] = 0.f;
        g_cnt[i] = 0;
        g_cur[i] = 0;
    }
}

// ---------------- histograms: deg[row] (float), cnt[col] (int) ----------------
__global__ void hist_kernel(const void* __restrict__ ei, int E) {
    int e = blockIdx.x * blockDim.x + threadIdx.x;
    if (e >= E) return;
    int is64 = g_is64;
    int r = load_idx(ei, e, is64);
    int c = load_idx(ei, (long long)E + e, is64);
    atomicAdd(&g_deg[r], 1.0f);
    atomicAdd(&g_cnt[c], 1);
}

// ---------------- exclusive scan of g_cnt into g_off (single block, shfl) ----------------
__global__ void __launch_bounds__(1024)
scan_kernel(int n) {
    __shared__ int warpsum[32];
    __shared__ int s_carry;
    const int tid  = threadIdx.x;
    const int lane = tid & 31;
    const int wid  = tid >> 5;
    if (tid == 0) { s_carry = 0; g_off[0] = 0; }
    __syncthreads();

    for (int base = 0; base < n; base += 1024) {
        int i = base + tid;
        int v = (i < n) ? g_cnt[i] : 0;
#pragma unroll
        for (int d = 1; d < 32; d <<= 1) {
            int t = __shfl_up_sync(0xffffffffu, v, d);
            if (lane >= d) v += t;
        }
        if (lane == 31) warpsum[wid] = v;
        __syncthreads();
        if (wid == 0) {
            int s = warpsum[lane];
#pragma unroll
            for (int d = 1; d < 32; d <<= 1) {
                int t = __shfl_up_sync(0xffffffffu, s, d);
                if (lane >= d) s += t;
            }
            warpsum[lane] = s;
        }
        __syncthreads();
        int add = (wid > 0) ? warpsum[wid - 1] : 0;
        int incl = s_carry + add + v;
        if (i < n) g_off[i + 1] = incl;
        __syncthreads();
        if (tid == 1023) s_carry = incl;
        __syncthreads();
    }
}

// ---------------- fused fill: compute norm inline, write into CSC bucket ----------------
__global__ void fill_kernel(const void* __restrict__ ei,
                            const float* __restrict__ edge_attr,
                            const float* __restrict__ conf_w,
                            const float* __restrict__ conf_b,
                            int E) {
    int e = blockIdx.x * blockDim.x + threadIdx.x;
    if (e >= E) return;
    int is64 = g_is64;
    int r = load_idx(ei, e, is64);
    int c = load_idx(ei, (long long)E + e, is64);

    float z = edge_attr[3 * e + 0] * conf_w[0]
            + edge_attr[3 * e + 1] * conf_w[1]
            + edge_attr[3 * e + 2] * conf_w[2]
            + conf_b[0];
    float ew = 1.0f / (1.0f + expf(-z));

    float dr = g_deg[r];
    float dc = g_deg[c];
    float ir = (dr > 0.f) ? rsqrtf(dr) : 0.f;
    float ic = (dc > 0.f) ? rsqrtf(dc) : 0.f;
    float nrm = ir * ic * ew;
    if (isnan(nrm)) nrm = 0.f;

    int pos = g_off[c] + atomicAdd(&g_cur[c], 1);
    g_srow[pos]  = r;
    g_snorm[pos] = nrm;
}

// ---------------- aggregate: one warp per destination node, 2-edge ILP ----------------
__global__ void __launch_bounds__(256)
aggregate_kernel(const float* __restrict__ x, int n_nodes) {
    int node = (blockIdx.x * blockDim.x + threadIdx.x) >> 5;
    int lane = threadIdx.x & 31;
    if (node >= n_nodes) return;

    int beg = g_off[node];
    int end = g_off[node + 1];

    float4 a0 = make_float4(0.f, 0.f, 0.f, 0.f);
    float4 a1 = a0, a2 = a0, a3 = a0;

    int i = beg;
    for (; i + 1 < end; i += 2) {
        int   rA  = g_srow[i];
        int   rB  = g_srow[i + 1];
        float nA  = g_snorm[i];
        float nB  = g_snorm[i + 1];
        const float4* xA = (const float4*)(x + (size_t)rA * D);
        const float4* xB = (const float4*)(x + (size_t)rB * D);
        float4 u0 = xA[lane];      float4 w0 = xB[lane];
        float4 u1 = xA[lane + 32]; float4 w1 = xB[lane + 32];
        float4 u2 = xA[lane + 64]; float4 w2 = xB[lane + 64];
        float4 u3 = xA[lane + 96]; float4 w3 = xB[lane + 96];
        a0.x = fmaf(u0.x, nA, a0.x); a0.y = fmaf(u0.y, nA, a0.y);
        a0.z = fmaf(u0.z, nA, a0.z); a0.w = fmaf(u0.w, nA, a0.w);
        a1.x = fmaf(u1.x, nA, a1.x); a1.y = fmaf(u1.y, nA, a1.y);
        a1.z = fmaf(u1.z, nA, a1.z); a1.w = fmaf(u1.w, nA, a1.w);
        a2.x = fmaf(u2.x, nA, a2.x); a2.y = fmaf(u2.y, nA, a2.y);
        a2.z = fmaf(u2.z, nA, a2.z); a2.w = fmaf(u2.w, nA, a2.w);
        a3.x = fmaf(u3.x, nA, a3.x); a3.y = fmaf(u3.y, nA, a3.y);
        a3.z = fmaf(u3.z, nA, a3.z); a3.w = fmaf(u3.w, nA, a3.w);
        a0.x = fmaf(w0.x, nB, a0.x); a0.y = fmaf(w0.y, nB, a0.y);
        a0.z = fmaf(w0.z, nB, a0.z); a0.w = fmaf(w0.w, nB, a0.w);
        a1.x = fmaf(w1.x, nB, a1.x); a1.y = fmaf(w1.y, nB, a1.y);
        a1.z = fmaf(w1.z, nB, a1.z); a1.w = fmaf(w1.w, nB, a1.w);
        a2.x = fmaf(w2.x, nB, a2.x); a2.y = fmaf(w2.y, nB, a2.y);
        a2.z = fmaf(w2.z, nB, a2.z); a2.w = fmaf(w2.w, nB, a2.w);
        a3.x = fmaf(w3.x, nB, a3.x); a3.y = fmaf(w3.y, nB, a3.y);
        a3.z = fmaf(w3.z, nB, a3.z); a3.w = fmaf(w3.w, nB, a3.w);
    }
    if (i < end) {
        int   r  = g_srow[i];
        float nm = g_snorm[i];
        const float4* xr = (const float4*)(x + (size_t)r * D);
        float4 v0 = xr[lane];
        float4 v1 = xr[lane + 32];
        float4 v2 = xr[lane + 64];
        float4 v3 = xr[lane + 96];
        a0.x = fmaf(v0.x, nm, a0.x); a0.y = fmaf(v0.y, nm, a0.y);
        a0.z = fmaf(v0.z, nm, a0.z); a0.w = fmaf(v0.w, nm, a0.w);
        a1.x = fmaf(v1.x, nm, a1.x); a1.y = fmaf(v1.y, nm, a1.y);
        a1.z = fmaf(v1.z, nm, a1.z); a1.w = fmaf(v1.w, nm, a1.w);
        a2.x = fmaf(v2.x, nm, a2.x); a2.y = fmaf(v2.y, nm, a2.y);
        a2.z = fmaf(v2.z, nm, a2.z); a2.w = fmaf(v2.w, nm, a2.w);
        a3.x = fmaf(v3.x, nm, a3.x); a3.y = fmaf(v3.y, nm, a3.y);
        a3.z = fmaf(v3.z, nm, a3.z); a3.w = fmaf(v3.w, nm, a3.w);
    }

    float4* dst = (float4*)(g_agg + (size_t)node * D);
    dst[lane]      = a0;
    dst[lane + 32] = a1;
    dst[lane + 64] = a2;
    dst[lane + 96] = a3;
}

// ---------------- TF32 tensor-core GEMM: out = agg @ W^T + b ----------------
// Block tile 128(m) x 128(n), 256 threads (8 warps as 2x4), warp tile 64x32.
#define KC       16
#define ROWPITCH 20

__device__ __forceinline__ void cp_async16(uint32_t smem, const void* gptr, int valid) {
    asm volatile("cp.async.cg.shared.global [%0], [%1], 16, %2;\n"
                 :: "r"(smem), "l"(gptr), "r"(valid ? 16 : 0));
}
__device__ __forceinline__ void cp_commit() {
    asm volatile("cp.async.commit_group;\n" ::: "memory");
}
__device__ __forceinline__ void cp_wait1() {
    asm volatile("cp.async.wait_group 1;\n" ::: "memory");
}
__device__ __forceinline__ uint32_t f2tf32(float f) {
    uint32_t u;
    asm("cvt.rna.tf32.f32 %0, %1;" : "=r"(u) : "f"(f));
    return u;
}

__global__ void __launch_bounds__(256)
gemm_tf32_kernel(const float* __restrict__ W,
                 const float* __restrict__ bias,
                 float* __restrict__ out,
                 int Nrows) {
    const float* __restrict__ A = g_agg;

    __shared__ float As[2][128 * ROWPITCH];
    __shared__ float Bs[2][128 * ROWPITCH];

    const int tid  = threadIdx.x;
    const int warp = tid >> 5;
    const int lane = tid & 31;
    const int g    = lane >> 2;
    const int tg   = lane & 3;
    const int wm   = warp >> 2;   // 0..1  (m)
    const int wn   = warp & 3;    // 0..3  (n)
    const int m0   = blockIdx.x * 128;
    const int n0   = blockIdx.y * 128;

    float acc[4][4][4];
#pragma unroll
    for (int i = 0; i < 4; i++)
#pragma unroll
        for (int j = 0; j < 4; j++)
#pragma unroll
            for (int r = 0; r < 4; r++) acc[i][j][r] = 0.f;

    uint32_t sA0 = (uint32_t)__cvta_generic_to_shared(&As[0][0]);
    uint32_t sA1 = (uint32_t)__cvta_generic_to_shared(&As[1][0]);
    uint32_t sB0 = (uint32_t)__cvta_generic_to_shared(&Bs[0][0]);
    uint32_t sB1 = (uint32_t)__cvta_generic_to_shared(&Bs[1][0]);

    // Loads per chunk: A 128x16 = 512 float4 (2/thread), B 128x16 (2/thread)
#define ISSUE_TILE(buf, k0)                                                        \
    do {                                                                           \
        uint32_t sa = (buf) ? sA1 : sA0;                                           \
        uint32_t sb = (buf) ? sB1 : sB0;                                           \
        _Pragma("unroll")                                                          \
        for (int i = 0; i < 2; i++) {                                              \
            int idx = i * 256 + tid;                                               \
            int row = idx >> 2, c4 = idx & 3;                                      \
            int grow = m0 + row;                                                   \
            const float* gp = A + (size_t)grow * D + (k0) + c4 * 4;                \
            cp_async16(sa + (row * ROWPITCH + c4 * 4) * 4, gp, grow < Nrows);      \
        }                                                                          \
        _Pragma("unroll")                                                          \
        for (int i = 0; i < 2; i++) {                                              \
            int idx = i * 256 + tid;                                               \
            int row = idx >> 2, c4 = idx & 3;                                      \
            const float* gp = W + (size_t)(n0 + row) * D + (k0) + c4 * 4;          \
            cp_async16(sb + (row * ROWPITCH + c4 * 4) * 4, gp, 1);                 \
        }                                                                          \
    } while (0)

    ISSUE_TILE(0, 0);
    cp_commit();

    const int NCHUNK = D / KC;
    for (int kc = 0; kc < NCHUNK; kc++) {
        int buf = kc & 1;
        if (kc + 1 < NCHUNK) ISSUE_TILE((kc + 1) & 1, (kc + 1) * KC);
        cp_commit();
        cp_wait1();
        __syncthreads();

        const float* as = As[buf];
        const float* bs = Bs[buf];

#pragma unroll
        for (int ks = 0; ks < 2; ks++) {
            int k = ks * 8;
            uint32_t af[4][4], bf[4][2];
#pragma unroll
            for (int mi = 0; mi < 4; mi++) {
                int rb = wm * 64 + mi * 16;
                af[mi][0] = f2tf32(as[(rb + g) * ROWPITCH + k + tg]);
                af[mi][1] = f2tf32(as[(rb + g + 8) * ROWPITCH + k + tg]);
                af[mi][2] = f2tf32(as[(rb + g) * ROWPITCH + k + tg + 4]);
                af[mi][3] = f2tf32(as[(rb + g + 8) * ROWPITCH + k + tg + 4]);
            }
#pragma unroll
            for (int nj = 0; nj < 4; nj++) {
                int nb = wn * 32 + nj * 8;
                bf[nj][0] = f2tf32(bs[(nb + g) * ROWPITCH + k + tg]);
                bf[nj][1] = f2tf32(bs[(nb + g) * ROWPITCH + k + tg + 4]);
            }
#pragma unroll
            for (int mi = 0; mi < 4; mi++)
#pragma unroll
                for (int nj = 0; nj < 4; nj++) {
                    asm volatile(
                        "mma.sync.aligned.m16n8k8.row.col.f32.tf32.tf32.f32 "
                        "{%0,%1,%2,%3}, {%4,%5,%6,%7}, {%8,%9}, {%0,%1,%2,%3};"
                        : "+f"(acc[mi][nj][0]), "+f"(acc[mi][nj][1]),
                          "+f"(acc[mi][nj][2]), "+f"(acc[mi][nj][3])
                        : "r"(af[mi][0]), "r"(af[mi][1]), "r"(af[mi][2]), "r"(af[mi][3]),
                          "r"(bf[nj][0]), "r"(bf[nj][1]));
                }
        }
        __syncthreads();
    }

#pragma unroll
    for (int mi = 0; mi < 4; mi++) {
        int r0 = m0 + wm * 64 + mi * 16 + g;
        int r1 = r0 + 8;
#pragma unroll
        for (int nj = 0; nj < 4; nj++) {
            int cn = n0 + wn * 32 + nj * 8 + 2 * tg;
            float2 bb = *(const float2*)(bias + cn);
            if (r0 < Nrows) {
                float2 v = make_float2(acc[mi][nj][0] + bb.x, acc[mi][nj][1] + bb.y);
                *(float2*)(out + (size_t)r0 * D + cn) = v;
            }
            if (r1 < Nrows) {
                float2 v = make_float2(acc[mi][nj][2] + bb.x, acc[mi][nj][3] + bb.y);
                *(float2*)(out + (size_t)r1 * D + cn) = v;
            }
        }
    }
#undef ISSUE_TILE
}

// ---------------- launch ----------------
extern "C" void kernel_launch(void* const* d_in, const int* in_sizes, int n_in,
                              void* d_out, int out_size) {
    const float* x         = (const float*)d_in[0];
    const void*  ei        = d_in[1];
    const float* edge_attr = (const float*)d_in[2];
    const float* lin_w     = (const float*)d_in[3];
    const float* lin_b     = (const float*)d_in[4];
    const float* conf_w    = (const float*)d_in[5];
    const float* conf_b    = (const float*)d_in[6];
    float* out             = (float*)d_out;

    const int n_nodes = in_sizes[0] / D;
    const int E       = in_sizes[2] / 3;

    detect_kernel<<<1, 256>>>((const int*)ei);
    zero_small_kernel<<<(n_nodes + 255) / 256, 256>>>(n_nodes);

    int eblocks = (E + 255) / 256;
    hist_kernel<<<eblocks, 256>>>(ei, E);
    scan_kernel<<<1, 1024>>>(n_nodes);
    fill_kernel<<<eblocks, 256>>>(ei, edge_attr, conf_w, conf_b, E);

    {
        int warps_per_block = 256 / 32;
        int blocks = (n_nodes + warps_per_block - 1) / warps_per_block;
        aggregate_kernel<<<blocks, 256>>>(x, n_nodes);
    }

    {
        dim3 grid((n_nodes + 127) / 128, D / 128);
        gemm_tf32_kernel<<<grid, 256>>>(lin_w, lin_b, out, n_nodes);
    }
}

// round 6
// speedup vs baseline: 3.1351x; 1.0864x over previous
#include <cuda_runtime.h>
#include <cstdint>

#define D        512
#define MAXN     50000
#define MAXE     800000
#define SCANB    ((MAXN + 1023) / 1024)   // 49 blocks

// ---------------- device scratch ----------------
__device__ float g_agg[(size_t)MAXN * D];   // aggregated messages [N, 512]
__device__ float g_deg[MAXN];               // source-degree (row histogram, as float)
__device__ int   g_cnt[MAXN];               // col histogram
__device__ int   g_off[MAXN + 1];           // CSC offsets
__device__ int   g_cur[MAXN];               // fill cursors
__device__ int   g_srow[MAXE];              // source row, sorted by destination
__device__ float g_snorm[MAXE];             // norm, sorted by destination
__device__ int   g_bsum[SCANB];             // per-block sums (scan phase A)
__device__ int   g_boff[SCANB];             // per-block exclusive offsets (phase B)
__device__ int   g_is64;

// ---------------- dtype sniffer ----------------
__global__ void detect_kernel(const int* __restrict__ ei32) {
    __shared__ int any_nonzero;
    if (threadIdx.x == 0) any_nonzero = 0;
    __syncthreads();
    int v = ei32[2 * threadIdx.x + 1];
    if (v != 0) atomicOr(&any_nonzero, 1);
    __syncthreads();
    if (threadIdx.x == 0) g_is64 = (any_nonzero == 0) ? 1 : 0;
}

__device__ __forceinline__ int load_idx(const void* ei, long long pos, int is64) {
    if (is64) return (int)((const long long*)ei)[pos];
    return ((const int*)ei)[pos];
}

// ---------------- zero the small arrays ----------------
__global__ void zero_small_kernel(int n_nodes) {
    int i = blockIdx.x * blockDim.x + threadIdx.x;
    if (i < n_nodes) {
        g_deg[i] = 0.f;
        g_cnt[i] = 0;
        g_cur[i] = 0;
    }
}

// ---------------- histograms: deg[row] (float), cnt[col] (int) ----------------
__global__ void hist_kernel(const void* __restrict__ ei, int E) {
    int e = blockIdx.x * blockDim.x + threadIdx.x;
    if (e >= E) return;
    int is64 = g_is64;
    int r = load_idx(ei, e, is64);
    int c = load_idx(ei, (long long)E + e, is64);
    atomicAdd(&g_deg[r], 1.0f);
    atomicAdd(&g_cnt[c], 1);
}

// ---------------- hierarchical scan ----------------
// Phase A: each block scans its 1024-chunk; writes inclusive scan (no offset)
// into g_off[i+1] and its block total into g_bsum[blockIdx.x].
__device__ __forceinline__ int block_scan_1024(int v, int* warpsum) {
    const int lane = threadIdx.x & 31;
    const int wid  = threadIdx.x >> 5;
#pragma unroll
    for (int d = 1; d < 32; d <<= 1) {
        int t = __shfl_up_sync(0xffffffffu, v, d);
        if (lane >= d) v += t;
    }
    if (lane == 31) warpsum[wid] = v;
    __syncthreads();
    if (wid == 0) {
        int s = warpsum[lane];
#pragma unroll
        for (int d = 1; d < 32; d <<= 1) {
            int t = __shfl_up_sync(0xffffffffu, s, d);
            if (lane >= d) s += t;
        }
        warpsum[lane] = s;
    }
    __syncthreads();
    return v + ((wid > 0) ? warpsum[wid - 1] : 0);
}

__global__ void __launch_bounds__(1024)
scanA_kernel(int n) {
    __shared__ int warpsum[32];
    int i = blockIdx.x * 1024 + threadIdx.x;
    int v = (i < n) ? g_cnt[i] : 0;
    int incl = block_scan_1024(v, warpsum);
    if (i < n) g_off[i + 1] = incl;
    if (threadIdx.x == 1023) g_bsum[blockIdx.x] = incl;
}

// Phase B: single block scans the per-block sums (SCANB <= 1024), exclusive.
__global__ void __launch_bounds__(1024)
scanB_kernel(int nb) {
    __shared__ int warpsum[32];
    int v = (threadIdx.x < nb) ? g_bsum[threadIdx.x] : 0;
    int incl = block_scan_1024(v, warpsum);
    if (threadIdx.x < nb) g_boff[threadIdx.x] = incl - v;   // exclusive
}

// Phase C: add block offsets; set g_off[0] = 0.
__global__ void __launch_bounds__(1024)
scanC_kernel(int n) {
    int i = blockIdx.x * 1024 + threadIdx.x;
    if (i == 0) g_off[0] = 0;
    if (i < n && blockIdx.x > 0) g_off[i + 1] += g_boff[blockIdx.x];
}

// ---------------- fused fill: compute norm inline, write into CSC bucket ----------------
__global__ void fill_kernel(const void* __restrict__ ei,
                            const float* __restrict__ edge_attr,
                            const float* __restrict__ conf_w,
                            const float* __restrict__ conf_b,
                            int E) {
    int e = blockIdx.x * blockDim.x + threadIdx.x;
    if (e >= E) return;
    int is64 = g_is64;
    int r = load_idx(ei, e, is64);
    int c = load_idx(ei, (long long)E + e, is64);

    float z = edge_attr[3 * e + 0] * conf_w[0]
            + edge_attr[3 * e + 1] * conf_w[1]
            + edge_attr[3 * e + 2] * conf_w[2]
            + conf_b[0];
    float ew = 1.0f / (1.0f + expf(-z));

    float dr = g_deg[r];
    float dc = g_deg[c];
    float ir = (dr > 0.f) ? rsqrtf(dr) : 0.f;
    float ic = (dc > 0.f) ? rsqrtf(dc) : 0.f;
    float nrm = ir * ic * ew;
    if (isnan(nrm)) nrm = 0.f;

    int pos = g_off[c] + atomicAdd(&g_cur[c], 1);
    g_srow[pos]  = r;
    g_snorm[pos] = nrm;
}

// ---------------- aggregate: one warp per destination node, 2-edge ILP ----------------
__global__ void __launch_bounds__(256)
aggregate_kernel(const float* __restrict__ x, int n_nodes) {
    int node = (blockIdx.x * blockDim.x + threadIdx.x) >> 5;
    int lane = threadIdx.x & 31;
    if (node >= n_nodes) return;

    int beg = g_off[node];
    int end = g_off[node + 1];

    float4 a0 = make_float4(0.f, 0.f, 0.f, 0.f);
    float4 a1 = a0, a2 = a0, a3 = a0;

    int i = beg;
    for (; i + 1 < end; i += 2) {
        int   rA  = g_srow[i];
        int   rB  = g_srow[i + 1];
        float nA  = g_snorm[i];
        float nB  = g_snorm[i + 1];
        const float4* xA = (const float4*)(x + (size_t)rA * D);
        const float4* xB = (const float4*)(x + (size_t)rB * D);
        float4 u0 = xA[lane];      float4 w0 = xB[lane];
        float4 u1 = xA[lane + 32]; float4 w1 = xB[lane + 32];
        float4 u2 = xA[lane + 64]; float4 w2 = xB[lane + 64];
        float4 u3 = xA[lane + 96]; float4 w3 = xB[lane + 96];
        a0.x = fmaf(u0.x, nA, a0.x); a0.y = fmaf(u0.y, nA, a0.y);
        a0.z = fmaf(u0.z, nA, a0.z); a0.w = fmaf(u0.w, nA, a0.w);
        a1.x = fmaf(u1.x, nA, a1.x); a1.y = fmaf(u1.y, nA, a1.y);
        a1.z = fmaf(u1.z, nA, a1.z); a1.w = fmaf(u1.w, nA, a1.w);
        a2.x = fmaf(u2.x, nA, a2.x); a2.y = fmaf(u2.y, nA, a2.y);
        a2.z = fmaf(u2.z, nA, a2.z); a2.w = fmaf(u2.w, nA, a2.w);
        a3.x = fmaf(u3.x, nA, a3.x); a3.y = fmaf(u3.y, nA, a3.y);
        a3.z = fmaf(u3.z, nA, a3.z); a3.w = fmaf(u3.w, nA, a3.w);
        a0.x = fmaf(w0.x, nB, a0.x); a0.y = fmaf(w0.y, nB, a0.y);
        a0.z = fmaf(w0.z, nB, a0.z); a0.w = fmaf(w0.w, nB, a0.w);
        a1.x = fmaf(w1.x, nB, a1.x); a1.y = fmaf(w1.y, nB, a1.y);
        a1.z = fmaf(w1.z, nB, a1.z); a1.w = fmaf(w1.w, nB, a1.w);
        a2.x = fmaf(w2.x, nB, a2.x); a2.y = fmaf(w2.y, nB, a2.y);
        a2.z = fmaf(w2.z, nB, a2.z); a2.w = fmaf(w2.w, nB, a2.w);
        a3.x = fmaf(w3.x, nB, a3.x); a3.y = fmaf(w3.y, nB, a3.y);
        a3.z = fmaf(w3.z, nB, a3.z); a3.w = fmaf(w3.w, nB, a3.w);
    }
    if (i < end) {
        int   r  = g_srow[i];
        float nm = g_snorm[i];
        const float4* xr = (const float4*)(x + (size_t)r * D);
        float4 v0 = xr[lane];
        float4 v1 = xr[lane + 32];
        float4 v2 = xr[lane + 64];
        float4 v3 = xr[lane + 96];
        a0.x = fmaf(v0.x, nm, a0.x); a0.y = fmaf(v0.y, nm, a0.y);
        a0.z = fmaf(v0.z, nm, a0.z); a0.w = fmaf(v0.w, nm, a0.w);
        a1.x = fmaf(v1.x, nm, a1.x); a1.y = fmaf(v1.y, nm, a1.y);
        a1.z = fmaf(v1.z, nm, a1.z); a1.w = fmaf(v1.w, nm, a1.w);
        a2.x = fmaf(v2.x, nm, a2.x); a2.y = fmaf(v2.y, nm, a2.y);
        a2.z = fmaf(v2.z, nm, a2.z); a2.w = fmaf(v2.w, nm, a2.w);
        a3.x = fmaf(v3.x, nm, a3.x); a3.y = fmaf(v3.y, nm, a3.y);
        a3.z = fmaf(v3.z, nm, a3.z); a3.w = fmaf(v3.w, nm, a3.w);
    }

    float4* dst = (float4*)(g_agg + (size_t)node * D);
    dst[lane]      = a0;
    dst[lane + 32] = a1;
    dst[lane + 64] = a2;
    dst[lane + 96] = a3;
}

// ---------------- TF32 tensor-core GEMM: out = agg @ W^T + b ----------------
// Block tile 128(m) x 128(n), 256 threads (8 warps as 2x4), warp tile 64x32.
#define KC       16
#define ROWPITCH 20

__device__ __forceinline__ void cp_async16(uint32_t smem, const void* gptr, int valid) {
    asm volatile("cp.async.cg.shared.global [%0], [%1], 16, %2;\n"
                 :: "r"(smem), "l"(gptr), "r"(valid ? 16 : 0));
}
__device__ __forceinline__ void cp_commit() {
    asm volatile("cp.async.commit_group;\n" ::: "memory");
}
__device__ __forceinline__ void cp_wait1() {
    asm volatile("cp.async.wait_group 1;\n" ::: "memory");
}
__device__ __forceinline__ uint32_t f2tf32(float f) {
    uint32_t u;
    asm("cvt.rna.tf32.f32 %0, %1;" : "=r"(u) : "f"(f));
    return u;
}

__global__ void __launch_bounds__(256)
gemm_tf32_kernel(const float* __restrict__ W,
                 const float* __restrict__ bias,
                 float* __restrict__ out,
                 int Nrows) {
    const float* __restrict__ A = g_agg;

    __shared__ float As[2][128 * ROWPITCH];
    __shared__ float Bs[2][128 * ROWPITCH];

    const int tid  = threadIdx.x;
    const int warp = tid >> 5;
    const int lane = tid & 31;
    const int g    = lane >> 2;
    const int tg   = lane & 3;
    const int wm   = warp >> 2;   // 0..1  (m)
    const int wn   = warp & 3;    // 0..3  (n)
    const int m0   = blockIdx.x * 128;
    const int n0   = blockIdx.y * 128;

    float acc[4][4][4];
#pragma unroll
    for (int i = 0; i < 4; i++)
#pragma unroll
        for (int j = 0; j < 4; j++)
#pragma unroll
            for (int r = 0; r < 4; r++) acc[i][j][r] = 0.f;

    uint32_t sA0 = (uint32_t)__cvta_generic_to_shared(&As[0][0]);
    uint32_t sA1 = (uint32_t)__cvta_generic_to_shared(&As[1][0]);
    uint32_t sB0 = (uint32_t)__cvta_generic_to_shared(&Bs[0][0]);
    uint32_t sB1 = (uint32_t)__cvta_generic_to_shared(&Bs[1][0]);

#define ISSUE_TILE(buf, k0)                                                        \
    do {                                                                           \
        uint32_t sa = (buf) ? sA1 : sA0;                                           \
        uint32_t sb = (buf) ? sB1 : sB0;                                           \
        _Pragma("unroll")                                                          \
        for (int i = 0; i < 2; i++) {                                              \
            int idx = i * 256 + tid;                                               \
            int row = idx >> 2, c4 = idx & 3;                                      \
            int grow = m0 + row;                                                   \
            const float* gp = A + (size_t)grow * D + (k0) + c4 * 4;                \
            cp_async16(sa + (row * ROWPITCH + c4 * 4) * 4, gp, grow < Nrows);      \
        }                                                                          \
        _Pragma("unroll")                                                          \
        for (int i = 0; i < 2; i++) {                                              \
            int idx = i * 256 + tid;                                               \
            int row = idx >> 2, c4 = idx & 3;                                      \
            const float* gp = W + (size_t)(n0 + row) * D + (k0) + c4 * 4;          \
            cp_async16(sb + (row * ROWPITCH + c4 * 4) * 4, gp, 1);                 \
        }                                                                          \
    } while (0)

    ISSUE_TILE(0, 0);
    cp_commit();

    const int NCHUNK = D / KC;
    for (int kc = 0; kc < NCHUNK; kc++) {
        int buf = kc & 1;
        if (kc + 1 < NCHUNK) ISSUE_TILE((kc + 1) & 1, (kc + 1) * KC);
        cp_commit();
        cp_wait1();
        __syncthreads();

        const float* as = As[buf];
        const float* bs = Bs[buf];

#pragma unroll
        for (int ks = 0; ks < 2; ks++) {
            int k = ks * 8;
            uint32_t af[4][4], bf[4][2];
#pragma unroll
            for (int mi = 0; mi < 4; mi++) {
                int rb = wm * 64 + mi * 16;
                af[mi][0] = f2tf32(as[(rb + g) * ROWPITCH + k + tg]);
                af[mi][1] = f2tf32(as[(rb + g + 8) * ROWPITCH + k + tg]);
                af[mi][2] = f2tf32(as[(rb + g) * ROWPITCH + k + tg + 4]);
                af[mi][3] = f2tf32(as[(rb + g + 8) * ROWPITCH + k + tg + 4]);
            }
#pragma unroll
            for (int nj = 0; nj < 4; nj++) {
                int nb = wn * 32 + nj * 8;
                bf[nj][0] = f2tf32(bs[(nb + g) * ROWPITCH + k + tg]);
                bf[nj][1] = f2tf32(bs[(nb + g) * ROWPITCH + k + tg + 4]);
            }
#pragma unroll
            for (int mi = 0; mi < 4; mi++)
#pragma unroll
                for (int nj = 0; nj < 4; nj++) {
                    asm volatile(
                        "mma.sync.aligned.m16n8k8.row.col.f32.tf32.tf32.f32 "
                        "{%0,%1,%2,%3}, {%4,%5,%6,%7}, {%8,%9}, {%0,%1,%2,%3};"
                        : "+f"(acc[mi][nj][0]), "+f"(acc[mi][nj][1]),
                          "+f"(acc[mi][nj][2]), "+f"(acc[mi][nj][3])
                        : "r"(af[mi][0]), "r"(af[mi][1]), "r"(af[mi][2]), "r"(af[mi][3]),
                          "r"(bf[nj][0]), "r"(bf[nj][1]));
                }
        }
        __syncthreads();
    }

#pragma unroll
    for (int mi = 0; mi < 4; mi++) {
        int r0 = m0 + wm * 64 + mi * 16 + g;
        int r1 = r0 + 8;
#pragma unroll
        for (int nj = 0; nj < 4; nj++) {
            int cn = n0 + wn * 32 + nj * 8 + 2 * tg;
            float2 bb = *(const float2*)(bias + cn);
            if (r0 < Nrows) {
                float2 v = make_float2(acc[mi][nj][0] + bb.x, acc[mi][nj][1] + bb.y);
                *(float2*)(out + (size_t)r0 * D + cn) = v;
            }
            if (r1 < Nrows) {
                float2 v = make_float2(acc[mi][nj][2] + bb.x, acc[mi][nj][3] + bb.y);
                *(float2*)(out + (size_t)r1 * D + cn) = v;
            }
        }
    }
#undef ISSUE_TILE
}

// ---------------- launch ----------------
extern "C" void kernel_launch(void* const* d_in, const int* in_sizes, int n_in,
                              void* d_out, int out_size) {
    const float* x         = (const float*)d_in[0];
    const void*  ei        = d_in[1];
    const float* edge_attr = (const float*)d_in[2];
    const float* lin_w     = (const float*)d_in[3];
    const float* lin_b     = (const float*)d_in[4];
    const float* conf_w    = (const float*)d_in[5];
    const float* conf_b    = (const float*)d_in[6];
    float* out             = (float*)d_out;

    const int n_nodes = in_sizes[0] / D;
    const int E       = in_sizes[2] / 3;
    const int nb      = (n_nodes + 1023) / 1024;

    detect_kernel<<<1, 256>>>((const int*)ei);
    zero_small_kernel<<<(n_nodes + 255) / 256, 256>>>(n_nodes);

    int eblocks = (E + 255) / 256;
    hist_kernel<<<eblocks, 256>>>(ei, E);

    scanA_kernel<<<nb, 1024>>>(n_nodes);
    scanB_kernel<<<1, 1024>>>(nb);
    scanC_kernel<<<nb, 1024>>>(n_nodes);

    fill_kernel<<<eblocks, 256>>>(ei, edge_attr, conf_w, conf_b, E);

    {
        int warps_per_block = 256 / 32;
        int blocks = (n_nodes + warps_per_block - 1) / warps_per_block;
        aggregate_kernel<<<blocks, 256>>>(x, n_nodes);
    }

    {
        dim3 grid((n_nodes + 127) / 128, D / 128);
        gemm_tf32_kernel<<<grid, 256>>>(lin_w, lin_b, out, n_nodes);
    }
}

// round 7
// speedup vs baseline: 3.4776x; 1.1092x over previous
#include <cuda_runtime.h>
#include <cuda_fp16.h>
#include <cstdint>

#define D        512
#define MAXN     50000
#define MAXE     800000
#define SCANB    ((MAXN + 1023) / 1024)   // 49 blocks

// ---------------- device scratch ----------------
__device__ float  g_agg[(size_t)MAXN * D];  // aggregated messages [N, 512] fp32
__device__ __half g_xh[(size_t)MAXN * D];   // x converted to fp16
__device__ float  g_deg[MAXN];              // source-degree
__device__ int    g_cnt[MAXN];              // col histogram
__device__ int    g_off[MAXN + 1];          // CSC offsets
__device__ int    g_cur[MAXN];              // fill cursors
__device__ int    g_srow[MAXE];             // source row, sorted by destination
__device__ float  g_snorm[MAXE];            // norm, sorted by destination
__device__ int    g_bsum[SCANB];
__device__ int    g_boff[SCANB];
__device__ int    g_is64;

// ---------------- dtype sniffer ----------------
__global__ void detect_kernel(const int* __restrict__ ei32) {
    __shared__ int any_nonzero;
    if (threadIdx.x == 0) any_nonzero = 0;
    __syncthreads();
    int v = ei32[2 * threadIdx.x + 1];
    if (v != 0) atomicOr(&any_nonzero, 1);
    __syncthreads();
    if (threadIdx.x == 0) g_is64 = (any_nonzero == 0) ? 1 : 0;
}

__device__ __forceinline__ int load_idx(const void* ei, long long pos, int is64) {
    if (is64) return (int)((const long long*)ei)[pos];
    return ((const int*)ei)[pos];
}

// ---------------- zero the small arrays ----------------
__global__ void zero_small_kernel(int n_nodes) {
    int i = blockIdx.x * blockDim.x + threadIdx.x;
    if (i < n_nodes) {
        g_deg[i] = 0.f;
        g_cnt[i] = 0;
        g_cur[i] = 0;
    }
}

// ---------------- convert x -> fp16 (8 floats / thread) ----------------
__global__ void convert_kernel(const float* __restrict__ x, int n_nodes) {
    size_t total8 = (size_t)n_nodes * D / 8;
    size_t i = (size_t)blockIdx.x * blockDim.x + threadIdx.x;
    size_t stride = (size_t)gridDim.x * blockDim.x;
    for (size_t k = i; k < total8; k += stride) {
        float4 f0 = ((const float4*)x)[2 * k];
        float4 f1 = ((const float4*)x)[2 * k + 1];
        __half2 h0 = __floats2half2_rn(f0.x, f0.y);
        __half2 h1 = __floats2half2_rn(f0.z, f0.w);
        __half2 h2 = __floats2half2_rn(f1.x, f1.y);
        __half2 h3 = __floats2half2_rn(f1.z, f1.w);
        uint4 packed;
        packed.x = *(uint32_t*)&h0;
        packed.y = *(uint32_t*)&h1;
        packed.z = *(uint32_t*)&h2;
        packed.w = *(uint32_t*)&h3;
        ((uint4*)g_xh)[k] = packed;
    }
}

// ---------------- histograms ----------------
__global__ void hist_kernel(const void* __restrict__ ei, int E) {
    int e = blockIdx.x * blockDim.x + threadIdx.x;
    if (e >= E) return;
    int is64 = g_is64;
    int r = load_idx(ei, e, is64);
    int c = load_idx(ei, (long long)E + e, is64);
    atomicAdd(&g_deg[r], 1.0f);
    atomicAdd(&g_cnt[c], 1);
}

// ---------------- hierarchical scan ----------------
__device__ __forceinline__ int block_scan_1024(int v, int* warpsum) {
    const int lane = threadIdx.x & 31;
    const int wid  = threadIdx.x >> 5;
#pragma unroll
    for (int d = 1; d < 32; d <<= 1) {
        int t = __shfl_up_sync(0xffffffffu, v, d);
        if (lane >= d) v += t;
    }
    if (lane == 31) warpsum[wid] = v;
    __syncthreads();
    if (wid == 0) {
        int s = warpsum[lane];
#pragma unroll
        for (int d = 1; d < 32; d <<= 1) {
            int t = __shfl_up_sync(0xffffffffu, s, d);
            if (lane >= d) s += t;
        }
        warpsum[lane] = s;
    }
    __syncthreads();
    return v + ((wid > 0) ? warpsum[wid - 1] : 0);
}

__global__ void __launch_bounds__(1024)
scanA_kernel(int n) {
    __shared__ int warpsum[32];
    int i = blockIdx.x * 1024 + threadIdx.x;
    int v = (i < n) ? g_cnt[i] : 0;
    int incl = block_scan_1024(v, warpsum);
    if (i < n) g_off[i + 1] = incl;
    if (threadIdx.x == 1023) g_bsum[blockIdx.x] = incl;
}

__global__ void __launch_bounds__(1024)
scanB_kernel(int nb) {
    __shared__ int warpsum[32];
    int v = (threadIdx.x < nb) ? g_bsum[threadIdx.x] : 0;
    int incl = block_scan_1024(v, warpsum);
    if (threadIdx.x < nb) g_boff[threadIdx.x] = incl - v;
}

__global__ void __launch_bounds__(1024)
scanC_kernel(int n) {
    int i = blockIdx.x * 1024 + threadIdx.x;
    if (i == 0) g_off[0] = 0;
    if (i < n && blockIdx.x > 0) g_off[i + 1] += g_boff[blockIdx.x];
}

// ---------------- fused fill ----------------
__global__ void fill_kernel(const void* __restrict__ ei,
                            const float* __restrict__ edge_attr,
                            const float* __restrict__ conf_w,
                            const float* __restrict__ conf_b,
                            int E) {
    int e = blockIdx.x * blockDim.x + threadIdx.x;
    if (e >= E) return;
    int is64 = g_is64;
    int r = load_idx(ei, e, is64);
    int c = load_idx(ei, (long long)E + e, is64);

    float z = edge_attr[3 * e + 0] * conf_w[0]
            + edge_attr[3 * e + 1] * conf_w[1]
            + edge_attr[3 * e + 2] * conf_w[2]
            + conf_b[0];
    float ew = 1.0f / (1.0f + expf(-z));

    float dr = g_deg[r];
    float dc = g_deg[c];
    float ir = (dr > 0.f) ? rsqrtf(dr) : 0.f;
    float ic = (dc > 0.f) ? rsqrtf(dc) : 0.f;
    float nrm = ir * ic * ew;
    if (isnan(nrm)) nrm = 0.f;

    int pos = g_off[c] + atomicAdd(&g_cur[c], 1);
    g_srow[pos]  = r;
    g_snorm[pos] = nrm;
}

// ---------------- aggregate (fp16 gather, fp32 accumulate) ----------------
// One warp per destination node. Row = 512 halves = 64 uint4.
// Lane l covers uint4 entries l and l+32 (16 halves). 2-edge ILP.
__device__ __forceinline__ void acc_u4(float2* a, uint4 u, float n) {
    const __half2* h = (const __half2*)&u;
#pragma unroll
    for (int j = 0; j < 4; j++) {
        float2 f = __half22float2(h[j]);
        a[j].x = fmaf(f.x, n, a[j].x);
        a[j].y = fmaf(f.y, n, a[j].y);
    }
}

__global__ void __launch_bounds__(256)
aggregate_kernel(int n_nodes) {
    int node = (blockIdx.x * blockDim.x + threadIdx.x) >> 5;
    int lane = threadIdx.x & 31;
    if (node >= n_nodes) return;

    int beg = g_off[node];
    int end = g_off[node + 1];

    float2 a[8];
#pragma unroll
    for (int j = 0; j < 8; j++) a[j] = make_float2(0.f, 0.f);

    int i = beg;
    for (; i + 1 < end; i += 2) {
        int   rA = g_srow[i];
        int   rB = g_srow[i + 1];
        float nA = g_snorm[i];
        float nB = g_snorm[i + 1];
        const uint4* xA = (const uint4*)(g_xh + (size_t)rA * D);
        const uint4* xB = (const uint4*)(g_xh + (size_t)rB * D);
        uint4 uA0 = xA[lane];
        uint4 uA1 = xA[lane + 32];
        uint4 uB0 = xB[lane];
        uint4 uB1 = xB[lane + 32];
        acc_u4(a,     uA0, nA);
        acc_u4(a + 4, uA1, nA);
        acc_u4(a,     uB0, nB);
        acc_u4(a + 4, uB1, nB);
    }
    if (i < end) {
        int   r  = g_srow[i];
        float nm = g_snorm[i];
        const uint4* xr = (const uint4*)(g_xh + (size_t)r * D);
        uint4 u0 = xr[lane];
        uint4 u1 = xr[lane + 32];
        acc_u4(a,     u0, nm);
        acc_u4(a + 4, u1, nm);
    }

    float4* dst = (float4*)(g_agg + (size_t)node * D);
    dst[2 * lane]              = make_float4(a[0].x, a[0].y, a[1].x, a[1].y);
    dst[2 * lane + 1]          = make_float4(a[2].x, a[2].y, a[3].x, a[3].y);
    dst[2 * (lane + 32)]       = make_float4(a[4].x, a[4].y, a[5].x, a[5].y);
    dst[2 * (lane + 32) + 1]   = make_float4(a[6].x, a[6].y, a[7].x, a[7].y);
}

// ---------------- TF32 tensor-core GEMM: out = agg @ W^T + b ----------------
#define KC       16
#define ROWPITCH 20

__device__ __forceinline__ void cp_async16(uint32_t smem, const void* gptr, int valid) {
    asm volatile("cp.async.cg.shared.global [%0], [%1], 16, %2;\n"
                 :: "r"(smem), "l"(gptr), "r"(valid ? 16 : 0));
}
__device__ __forceinline__ void cp_commit() {
    asm volatile("cp.async.commit_group;\n" ::: "memory");
}
__device__ __forceinline__ void cp_wait1() {
    asm volatile("cp.async.wait_group 1;\n" ::: "memory");
}
__device__ __forceinline__ uint32_t f2tf32(float f) {
    uint32_t u;
    asm("cvt.rna.tf32.f32 %0, %1;" : "=r"(u) : "f"(f));
    return u;
}

__global__ void __launch_bounds__(256)
gemm_tf32_kernel(const float* __restrict__ W,
                 const float* __restrict__ bias,
                 float* __restrict__ out,
                 int Nrows) {
    const float* __restrict__ A = g_agg;

    __shared__ float As[2][128 * ROWPITCH];
    __shared__ float Bs[2][128 * ROWPITCH];

    const int tid  = threadIdx.x;
    const int warp = tid >> 5;
    const int lane = tid & 31;
    const int g    = lane >> 2;
    const int tg   = lane & 3;
    const int wm   = warp >> 2;   // 0..1
    const int wn   = warp & 3;    // 0..3
    const int m0   = blockIdx.x * 128;
    const int n0   = blockIdx.y * 128;

    float acc[4][4][4];
#pragma unroll
    for (int i = 0; i < 4; i++)
#pragma unroll
        for (int j = 0; j < 4; j++)
#pragma unroll
            for (int r = 0; r < 4; r++) acc[i][j][r] = 0.f;

    uint32_t sA0 = (uint32_t)__cvta_generic_to_shared(&As[0][0]);
    uint32_t sA1 = (uint32_t)__cvta_generic_to_shared(&As[1][0]);
    uint32_t sB0 = (uint32_t)__cvta_generic_to_shared(&Bs[0][0]);
    uint32_t sB1 = (uint32_t)__cvta_generic_to_shared(&Bs[1][0]);

#define ISSUE_TILE(buf, k0)                                                        \
    do {                                                                           \
        uint32_t sa = (buf) ? sA1 : sA0;                                           \
        uint32_t sb = (buf) ? sB1 : sB0;                                           \
        _Pragma("unroll")                                                          \
        for (int i = 0; i < 2; i++) {                                              \
            int idx = i * 256 + tid;                                               \
            int row = idx >> 2, c4 = idx & 3;                                      \
            int grow = m0 + row;                                                   \
            const float* gp = A + (size_t)grow * D + (k0) + c4 * 4;                \
            cp_async16(sa + (row * ROWPITCH + c4 * 4) * 4, gp, grow < Nrows);      \
        }                                                                          \
        _Pragma("unroll")                                                          \
        for (int i = 0; i < 2; i++) {                                              \
            int idx = i * 256 + tid;                                               \
            int row = idx >> 2, c4 = idx & 3;                                      \
            const float* gp = W + (size_t)(n0 + row) * D + (k0) + c4 * 4;          \
            cp_async16(sb + (row * ROWPITCH + c4 * 4) * 4, gp, 1);                 \
        }                                                                          \
    } while (0)

    ISSUE_TILE(0, 0);
    cp_commit();

    const int NCHUNK = D / KC;
    for (int kc = 0; kc < NCHUNK; kc++) {
        int buf = kc & 1;
        if (kc + 1 < NCHUNK) ISSUE_TILE((kc + 1) & 1, (kc + 1) * KC);
        cp_commit();
        cp_wait1();
        __syncthreads();

        const float* as = As[buf];
        const float* bs = Bs[buf];

#pragma unroll
        for (int ks = 0; ks < 2; ks++) {
            int k = ks * 8;
            uint32_t af[4][4], bf[4][2];
#pragma unroll
            for (int mi = 0; mi < 4; mi++) {
                int rb = wm * 64 + mi * 16;
                af[mi][0] = f2tf32(as[(rb + g) * ROWPITCH + k + tg]);
                af[mi][1] = f2tf32(as[(rb + g + 8) * ROWPITCH + k + tg]);
                af[mi][2] = f2tf32(as[(rb + g) * ROWPITCH + k + tg + 4]);
                af[mi][3] = f2tf32(as[(rb + g + 8) * ROWPITCH + k + tg + 4]);
            }
#pragma unroll
            for (int nj = 0; nj < 4; nj++) {
                int nb = wn * 32 + nj * 8;
                bf[nj][0] = f2tf32(bs[(nb + g) * ROWPITCH + k + tg]);
                bf[nj][1] = f2tf32(bs[(nb + g) * ROWPITCH + k + tg + 4]);
            }
#pragma unroll
            for (int mi = 0; mi < 4; mi++)
#pragma unroll
                for (int nj = 0; nj < 4; nj++) {
                    asm volatile(
                        "mma.sync.aligned.m16n8k8.row.col.f32.tf32.tf32.f32 "
                        "{%0,%1,%2,%3}, {%4,%5,%6,%7}, {%8,%9}, {%0,%1,%2,%3};"
                        : "+f"(acc[mi][nj][0]), "+f"(acc[mi][nj][1]),
                          "+f"(acc[mi][nj][2]), "+f"(acc[mi][nj][3])
                        : "r"(af[mi][0]), "r"(af[mi][1]), "r"(af[mi][2]), "r"(af[mi][3]),
                          "r"(bf[nj][0]), "r"(bf[nj][1]));
                }
        }
        __syncthreads();
    }

#pragma unroll
    for (int mi = 0; mi < 4; mi++) {
        int r0 = m0 + wm * 64 + mi * 16 + g;
        int r1 = r0 + 8;
#pragma unroll
        for (int nj = 0; nj < 4; nj++) {
            int cn = n0 + wn * 32 + nj * 8 + 2 * tg;
            float2 bb = *(const float2*)(bias + cn);
            if (r0 < Nrows) {
                float2 v = make_float2(acc[mi][nj][0] + bb.x, acc[mi][nj][1] + bb.y);
                *(float2*)(out + (size_t)r0 * D + cn) = v;
            }
            if (r1 < Nrows) {
                float2 v = make_float2(acc[mi][nj][2] + bb.x, acc[mi][nj][3] + bb.y);
                *(float2*)(out + (size_t)r1 * D + cn) = v;
            }
        }
    }
#undef ISSUE_TILE
}

// ---------------- launch ----------------
extern "C" void kernel_launch(void* const* d_in, const int* in_sizes, int n_in,
                              void* d_out, int out_size) {
    const float* x         = (const float*)d_in[0];
    const void*  ei        = d_in[1];
    const float* edge_attr = (const float*)d_in[2];
    const float* lin_w     = (const float*)d_in[3];
    const float* lin_b     = (const float*)d_in[4];
    const float* conf_w    = (const float*)d_in[5];
    const float* conf_b    = (const float*)d_in[6];
    float* out             = (float*)d_out;

    const int n_nodes = in_sizes[0] / D;
    const int E       = in_sizes[2] / 3;
    const int nb      = (n_nodes + 1023) / 1024;

    detect_kernel<<<1, 256>>>((const int*)ei);
    zero_small_kernel<<<(n_nodes + 255) / 256, 256>>>(n_nodes);
    convert_kernel<<<1024, 256>>>(x, n_nodes);

    int eblocks = (E + 255) / 256;
    hist_kernel<<<eblocks, 256>>>(ei, E);

    scanA_kernel<<<nb, 1024>>>(n_nodes);
    scanB_kernel<<<1, 1024>>>(nb);
    scanC_kernel<<<nb, 1024>>>(n_nodes);

    fill_kernel<<<eblocks, 256>>>(ei, edge_attr, conf_w, conf_b, E);

    {
        int warps_per_block = 256 / 32;
        int blocks = (n_nodes + warps_per_block - 1) / warps_per_block;
        aggregate_kernel<<<blocks, 256>>>(n_nodes);
    }

    {
        dim3 grid((n_nodes + 127) / 128, D / 128);
        gemm_tf32_kernel<<<grid, 256>>>(lin_w, lin_b, out, n_nodes);
    }
}

// round 8
// speedup vs baseline: 4.6494x; 1.3370x over previous
#include <cuda_runtime.h>
#include <cuda_fp16.h>
#include <cstdint>

#define D        512
#define MAXN     50000
#define MAXE     800000
#define SCANB    ((MAXN + 1023) / 1024)   // 49 blocks

// ---------------- device scratch ----------------
__device__ __half g_aggh[(size_t)MAXN * D]; // aggregated messages [N, 512] fp16
__device__ __half g_xh[(size_t)MAXN * D];   // x converted to fp16
__device__ __half g_wh[(size_t)D * D];      // W converted to fp16 [n][k]
__device__ float  g_deg[MAXN];              // source-degree
__device__ int    g_cnt[MAXN];              // col histogram
__device__ int    g_off[MAXN + 1];          // CSC offsets
__device__ int    g_cur[MAXN];              // fill cursors
__device__ int    g_srow[MAXE];             // source row, sorted by destination
__device__ float  g_snorm[MAXE];            // norm, sorted by destination
__device__ int    g_bsum[SCANB];
__device__ int    g_boff[SCANB];
__device__ int    g_is64;

// ---------------- dtype sniffer ----------------
__global__ void detect_kernel(const int* __restrict__ ei32) {
    __shared__ int any_nonzero;
    if (threadIdx.x == 0) any_nonzero = 0;
    __syncthreads();
    int v = ei32[2 * threadIdx.x + 1];
    if (v != 0) atomicOr(&any_nonzero, 1);
    __syncthreads();
    if (threadIdx.x == 0) g_is64 = (any_nonzero == 0) ? 1 : 0;
}

__device__ __forceinline__ int load_idx(const void* ei, long long pos, int is64) {
    if (is64) return (int)((const long long*)ei)[pos];
    return ((const int*)ei)[pos];
}

// ---------------- zero the small arrays ----------------
__global__ void zero_small_kernel(int n_nodes) {
    int i = blockIdx.x * blockDim.x + threadIdx.x;
    if (i < n_nodes) {
        g_deg[i] = 0.f;
        g_cnt[i] = 0;
        g_cur[i] = 0;
    }
}

// ---------------- convert x -> fp16 ----------------
__global__ void convert_kernel(const float* __restrict__ x, int n_nodes) {
    size_t total8 = (size_t)n_nodes * D / 8;
    size_t i = (size_t)blockIdx.x * blockDim.x + threadIdx.x;
    size_t stride = (size_t)gridDim.x * blockDim.x;
    for (size_t k = i; k < total8; k += stride) {
        float4 f0 = ((const float4*)x)[2 * k];
        float4 f1 = ((const float4*)x)[2 * k + 1];
        __half2 h0 = __floats2half2_rn(f0.x, f0.y);
        __half2 h1 = __floats2half2_rn(f0.z, f0.w);
        __half2 h2 = __floats2half2_rn(f1.x, f1.y);
        __half2 h3 = __floats2half2_rn(f1.z, f1.w);
        uint4 packed;
        packed.x = *(uint32_t*)&h0;
        packed.y = *(uint32_t*)&h1;
        packed.z = *(uint32_t*)&h2;
        packed.w = *(uint32_t*)&h3;
        ((uint4*)g_xh)[k] = packed;
    }
}

// ---------------- convert W -> fp16 ----------------
__global__ void wconvert_kernel(const float* __restrict__ W) {
    size_t total8 = (size_t)D * D / 8;
    size_t i = (size_t)blockIdx.x * blockDim.x + threadIdx.x;
    size_t stride = (size_t)gridDim.x * blockDim.x;
    for (size_t k = i; k < total8; k += stride) {
        float4 f0 = ((const float4*)W)[2 * k];
        float4 f1 = ((const float4*)W)[2 * k + 1];
        __half2 h0 = __floats2half2_rn(f0.x, f0.y);
        __half2 h1 = __floats2half2_rn(f0.z, f0.w);
        __half2 h2 = __floats2half2_rn(f1.x, f1.y);
        __half2 h3 = __floats2half2_rn(f1.z, f1.w);
        uint4 packed;
        packed.x = *(uint32_t*)&h0;
        packed.y = *(uint32_t*)&h1;
        packed.z = *(uint32_t*)&h2;
        packed.w = *(uint32_t*)&h3;
        ((uint4*)g_wh)[k] = packed;
    }
}

// ---------------- histograms ----------------
__global__ void hist_kernel(const void* __restrict__ ei, int E) {
    int e = blockIdx.x * blockDim.x + threadIdx.x;
    if (e >= E) return;
    int is64 = g_is64;
    int r = load_idx(ei, e, is64);
    int c = load_idx(ei, (long long)E + e, is64);
    atomicAdd(&g_deg[r], 1.0f);
    atomicAdd(&g_cnt[c], 1);
}

// ---------------- hierarchical scan ----------------
__device__ __forceinline__ int block_scan_1024(int v, int* warpsum) {
    const int lane = threadIdx.x & 31;
    const int wid  = threadIdx.x >> 5;
#pragma unroll
    for (int d = 1; d < 32; d <<= 1) {
        int t = __shfl_up_sync(0xffffffffu, v, d);
        if (lane >= d) v += t;
    }
    if (lane == 31) warpsum[wid] = v;
    __syncthreads();
    if (wid == 0) {
        int s = warpsum[lane];
#pragma unroll
        for (int d = 1; d < 32; d <<= 1) {
            int t = __shfl_up_sync(0xffffffffu, s, d);
            if (lane >= d) s += t;
        }
        warpsum[lane] = s;
    }
    __syncthreads();
    return v + ((wid > 0) ? warpsum[wid - 1] : 0);
}

__global__ void __launch_bounds__(1024)
scanA_kernel(int n) {
    __shared__ int warpsum[32];
    int i = blockIdx.x * 1024 + threadIdx.x;
    int v = (i < n) ? g_cnt[i] : 0;
    int incl = block_scan_1024(v, warpsum);
    if (i < n) g_off[i + 1] = incl;
    if (threadIdx.x == 1023) g_bsum[blockIdx.x] = incl;
}

__global__ void __launch_bounds__(1024)
scanB_kernel(int nb) {
    __shared__ int warpsum[32];
    int v = (threadIdx.x < nb) ? g_bsum[threadIdx.x] : 0;
    int incl = block_scan_1024(v, warpsum);
    if (threadIdx.x < nb) g_boff[threadIdx.x] = incl - v;
}

__global__ void __launch_bounds__(1024)
scanC_kernel(int n) {
    int i = blockIdx.x * 1024 + threadIdx.x;
    if (i == 0) g_off[0] = 0;
    if (i < n && blockIdx.x > 0) g_off[i + 1] += g_boff[blockIdx.x];
}

// ---------------- fused fill ----------------
__global__ void fill_kernel(const void* __restrict__ ei,
                            const float* __restrict__ edge_attr,
                            const float* __restrict__ conf_w,
                            const float* __restrict__ conf_b,
                            int E) {
    int e = blockIdx.x * blockDim.x + threadIdx.x;
    if (e >= E) return;
    int is64 = g_is64;
    int r = load_idx(ei, e, is64);
    int c = load_idx(ei, (long long)E + e, is64);

    float z = edge_attr[3 * e + 0] * conf_w[0]
            + edge_attr[3 * e + 1] * conf_w[1]
            + edge_attr[3 * e + 2] * conf_w[2]
            + conf_b[0];
    float ew = 1.0f / (1.0f + expf(-z));

    float dr = g_deg[r];
    float dc = g_deg[c];
    float ir = (dr > 0.f) ? rsqrtf(dr) : 0.f;
    float ic = (dc > 0.f) ? rsqrtf(dc) : 0.f;
    float nrm = ir * ic * ew;
    if (isnan(nrm)) nrm = 0.f;

    int pos = g_off[c] + atomicAdd(&g_cur[c], 1);
    g_srow[pos]  = r;
    g_snorm[pos] = nrm;
}

// ---------------- aggregate (fp16 gather, fp32 accumulate, fp16 out) ----------------
__device__ __forceinline__ void acc_u4(float2* a, uint4 u, float n) {
    const __half2* h = (const __half2*)&u;
#pragma unroll
    for (int j = 0; j < 4; j++) {
        float2 f = __half22float2(h[j]);
        a[j].x = fmaf(f.x, n, a[j].x);
        a[j].y = fmaf(f.y, n, a[j].y);
    }
}

__global__ void __launch_bounds__(256)
aggregate_kernel(int n_nodes) {
    int node = (blockIdx.x * blockDim.x + threadIdx.x) >> 5;
    int lane = threadIdx.x & 31;
    if (node >= n_nodes) return;

    int beg = g_off[node];
    int end = g_off[node + 1];

    float2 a[8];
#pragma unroll
    for (int j = 0; j < 8; j++) a[j] = make_float2(0.f, 0.f);

    int i = beg;
    for (; i + 1 < end; i += 2) {
        int   rA = g_srow[i];
        int   rB = g_srow[i + 1];
        float nA = g_snorm[i];
        float nB = g_snorm[i + 1];
        const uint4* xA = (const uint4*)(g_xh + (size_t)rA * D);
        const uint4* xB = (const uint4*)(g_xh + (size_t)rB * D);
        uint4 uA0 = xA[lane];
        uint4 uA1 = xA[lane + 32];
        uint4 uB0 = xB[lane];
        uint4 uB1 = xB[lane + 32];
        acc_u4(a,     uA0, nA);
        acc_u4(a + 4, uA1, nA);
        acc_u4(a,     uB0, nB);
        acc_u4(a + 4, uB1, nB);
    }
    if (i < end) {
        int   r  = g_srow[i];
        float nm = g_snorm[i];
        const uint4* xr = (const uint4*)(g_xh + (size_t)r * D);
        uint4 u0 = xr[lane];
        uint4 u1 = xr[lane + 32];
        acc_u4(a,     u0, nm);
        acc_u4(a + 4, u1, nm);
    }

    // pack to fp16 and store: uint4 index 'lane' holds halves 8*lane..8*lane+7
    uint4* dst = (uint4*)(g_aggh + (size_t)node * D);
    uint4 o0, o1;
    __half2 t;
    t = __floats2half2_rn(a[0].x, a[0].y); o0.x = *(uint32_t*)&t;
    t = __floats2half2_rn(a[1].x, a[1].y); o0.y = *(uint32_t*)&t;
    t = __floats2half2_rn(a[2].x, a[2].y); o0.z = *(uint32_t*)&t;
    t = __floats2half2_rn(a[3].x, a[3].y); o0.w = *(uint32_t*)&t;
    t = __floats2half2_rn(a[4].x, a[4].y); o1.x = *(uint32_t*)&t;
    t = __floats2half2_rn(a[5].x, a[5].y); o1.y = *(uint32_t*)&t;
    t = __floats2half2_rn(a[6].x, a[6].y); o1.z = *(uint32_t*)&t;
    t = __floats2half2_rn(a[7].x, a[7].y); o1.w = *(uint32_t*)&t;
    dst[lane]      = o0;
    dst[lane + 32] = o1;
}

// ---------------- FP16 tensor-core GEMM: out = aggh @ Wh^T + b ----------------
// Block tile 128(m) x 128(n), 256 threads (8 warps as 2x4), warp tile 64x32.
// mma.sync m16n8k16 f16 inputs, f32 accumulate. K-chunk 32, double buffered.
#define KC       32            // k halves per chunk
#define HPITCH   40            // halves per smem row (32 data + 8 pad); 20-word pitch conflict-free

__device__ __forceinline__ void cp_async16(uint32_t smem, const void* gptr, int valid) {
    asm volatile("cp.async.cg.shared.global [%0], [%1], 16, %2;\n"
                 :: "r"(smem), "l"(gptr), "r"(valid ? 16 : 0));
}
__device__ __forceinline__ void cp_commit() {
    asm volatile("cp.async.commit_group;\n" ::: "memory");
}
__device__ __forceinline__ void cp_wait1() {
    asm volatile("cp.async.wait_group 1;\n" ::: "memory");
}

__global__ void __launch_bounds__(256)
gemm_fp16_kernel(const float* __restrict__ bias,
                 float* __restrict__ out,
                 int Nrows) {
    const __half* __restrict__ A = g_aggh;   // [N, 512]
    const __half* __restrict__ B = g_wh;     // [512, 512] row-major [n][k]

    __shared__ __half As[2][128 * HPITCH];
    __shared__ __half Bs[2][128 * HPITCH];

    const int tid  = threadIdx.x;
    const int warp = tid >> 5;
    const int lane = tid & 31;
    const int g    = lane >> 2;   // 0..7
    const int tg   = lane & 3;    // 0..3
    const int wm   = warp >> 2;   // 0..1  (m)
    const int wn   = warp & 3;    // 0..3  (n)
    const int m0   = blockIdx.x * 128;
    const int n0   = blockIdx.y * 128;

    float acc[4][4][4];
#pragma unroll
    for (int i = 0; i < 4; i++)
#pragma unroll
        for (int j = 0; j < 4; j++)
#pragma unroll
            for (int r = 0; r < 4; r++) acc[i][j][r] = 0.f;

    uint32_t sA0 = (uint32_t)__cvta_generic_to_shared(&As[0][0]);
    uint32_t sA1 = (uint32_t)__cvta_generic_to_shared(&As[1][0]);
    uint32_t sB0 = (uint32_t)__cvta_generic_to_shared(&Bs[0][0]);
    uint32_t sB1 = (uint32_t)__cvta_generic_to_shared(&Bs[1][0]);

    // A tile 128x32 halves: 512 chunks of 8 halves (16B); 256 thr -> 2 each. Same B.
#define ISSUE_TILE(buf, k0)                                                          \
    do {                                                                             \
        uint32_t sa = (buf) ? sA1 : sA0;                                             \
        uint32_t sb = (buf) ? sB1 : sB0;                                             \
        _Pragma("unroll")                                                            \
        for (int i = 0; i < 2; i++) {                                                \
            int idx = i * 256 + tid;                                                 \
            int row = idx >> 2, c8 = idx & 3;                                        \
            int grow = m0 + row;                                                     \
            const __half* gp = A + (size_t)grow * D + (k0) + c8 * 8;                 \
            cp_async16(sa + (row * HPITCH + c8 * 8) * 2, gp, grow < Nrows);          \
        }                                                                            \
        _Pragma("unroll")                                                            \
        for (int i = 0; i < 2; i++) {                                                \
            int idx = i * 256 + tid;                                                 \
            int row = idx >> 2, c8 = idx & 3;                                        \
            const __half* gp = B + (size_t)(n0 + row) * D + (k0) + c8 * 8;           \
            cp_async16(sb + (row * HPITCH + c8 * 8) * 2, gp, 1);                     \
        }                                                                            \
    } while (0)

    ISSUE_TILE(0, 0);
    cp_commit();

    const int NCHUNK = D / KC;   // 16
    for (int kc = 0; kc < NCHUNK; kc++) {
        int buf = kc & 1;
        if (kc + 1 < NCHUNK) ISSUE_TILE((kc + 1) & 1, (kc + 1) * KC);
        cp_commit();
        cp_wait1();
        __syncthreads();

        const __half* as = As[buf];
        const __half* bs = Bs[buf];

#pragma unroll
        for (int ks = 0; ks < 2; ks++) {
            int kk = ks * 16;
            uint32_t af[4][4], bf[4][2];
#pragma unroll
            for (int mi = 0; mi < 4; mi++) {
                int rb = wm * 64 + mi * 16;
                af[mi][0] = *(const uint32_t*)(as + (rb + g)     * HPITCH + kk + 2 * tg);
                af[mi][1] = *(const uint32_t*)(as + (rb + g + 8) * HPITCH + kk + 2 * tg);
                af[mi][2] = *(const uint32_t*)(as + (rb + g)     * HPITCH + kk + 2 * tg + 8);
                af[mi][3] = *(const uint32_t*)(as + (rb + g + 8) * HPITCH + kk + 2 * tg + 8);
            }
#pragma unroll
            for (int nj = 0; nj < 4; nj++) {
                int nb = wn * 32 + nj * 8;
                bf[nj][0] = *(const uint32_t*)(bs + (nb + g) * HPITCH + kk + 2 * tg);
                bf[nj][1] = *(const uint32_t*)(bs + (nb + g) * HPITCH + kk + 2 * tg + 8);
            }
#pragma unroll
            for (int mi = 0; mi < 4; mi++)
#pragma unroll
                for (int nj = 0; nj < 4; nj++) {
                    asm volatile(
                        "mma.sync.aligned.m16n8k16.row.col.f32.f16.f16.f32 "
                        "{%0,%1,%2,%3}, {%4,%5,%6,%7}, {%8,%9}, {%0,%1,%2,%3};"
                        : "+f"(acc[mi][nj][0]), "+f"(acc[mi][nj][1]),
                          "+f"(acc[mi][nj][2]), "+f"(acc[mi][nj][3])
                        : "r"(af[mi][0]), "r"(af[mi][1]), "r"(af[mi][2]), "r"(af[mi][3]),
                          "r"(bf[nj][0]), "r"(bf[nj][1]));
                }
        }
        __syncthreads();
    }

#pragma unroll
    for (int mi = 0; mi < 4; mi++) {
        int r0 = m0 + wm * 64 + mi * 16 + g;
        int r1 = r0 + 8;
#pragma unroll
        for (int nj = 0; nj < 4; nj++) {
            int cn = n0 + wn * 32 + nj * 8 + 2 * tg;
            float2 bb = *(const float2*)(bias + cn);
            if (r0 < Nrows) {
                float2 v = make_float2(acc[mi][nj][0] + bb.x, acc[mi][nj][1] + bb.y);
                *(float2*)(out + (size_t)r0 * D + cn) = v;
            }
            if (r1 < Nrows) {
                float2 v = make_float2(acc[mi][nj][2] + bb.x, acc[mi][nj][3] + bb.y);
                *(float2*)(out + (size_t)r1 * D + cn) = v;
            }
        }
    }
#undef ISSUE_TILE
}

// ---------------- launch ----------------
extern "C" void kernel_launch(void* const* d_in, const int* in_sizes, int n_in,
                              void* d_out, int out_size) {
    const float* x         = (const float*)d_in[0];
    const void*  ei        = d_in[1];
    const float* edge_attr = (const float*)d_in[2];
    const float* lin_w     = (const float*)d_in[3];
    const float* lin_b     = (const float*)d_in[4];
    const float* conf_w    = (const float*)d_in[5];
    const float* conf_b    = (const float*)d_in[6];
    float* out             = (float*)d_out;

    const int n_nodes = in_sizes[0] / D;
    const int E       = in_sizes[2] / 3;
    const int nb      = (n_nodes + 1023) / 1024;

    detect_kernel<<<1, 256>>>((const int*)ei);
    zero_small_kernel<<<(n_nodes + 255) / 256, 256>>>(n_nodes);
    convert_kernel<<<1024, 256>>>(x, n_nodes);
    wconvert_kernel<<<128, 256>>>(lin_w);

    int eblocks = (E + 255) / 256;
    hist_kernel<<<eblocks, 256>>>(ei, E);

    scanA_kernel<<<nb, 1024>>>(n_nodes);
    scanB_kernel<<<1, 1024>>>(nb);
    scanC_kernel<<<nb, 1024>>>(n_nodes);

    fill_kernel<<<eblocks, 256>>>(ei, edge_attr, conf_w, conf_b, E);

    {
        int warps_per_block = 256 / 32;
        int blocks = (n_nodes + warps_per_block - 1) / warps_per_block;
        aggregate_kernel<<<blocks, 256>>>(n_nodes);
    }

    {
        dim3 grid((n_nodes + 127) / 128, D / 128);
        gemm_fp16_kernel<<<grid, 256>>>(lin_b, out, n_nodes);
    }
}